// round 1
// baseline (speedup 1.0000x reference)
#include <cuda_runtime.h>
#include <cuda_bf16.h>

#define Hd 1024
#define Bd 64
#define Sd 512
#define NCd 20
#define NNd 15
#define OPd 5
#define NTOT 35
#define NEGV (-1e12f)

// ---------------- scratch (device globals; no allocation allowed) ----------------
__device__ float g_pre[4 * Bd * Hd];        // preacts: l, lg, r, rg
__device__ float g_lc[Bd * 2 * Hd];         // [left_childs | cur_emb]
__device__ float g_node[Bd * Hd];
__device__ float g_cnode[Bd * Hd];          // Wa[:, :H]*node + ba
__device__ float g_energy[Bd * Sd];         // energies -> attn weights
__device__ float g_ctx[Bd * Hd];
__device__ float g_cat[Bd * 2 * Hd];        // [node | ctx]
__device__ float g_leafpre[Bd * Hd];
__device__ float g_leaf[Bd * Hd];
__device__ float g_cnum[Bd * Hd];           // Wna[:, :H]*leaf + bna
__device__ float g_cop[Bd * Hd];            // Woa[:, :H]*leaf + boa
__device__ float g_aextn[Bd * NTOT * 2 * Hd]; // [emb | leaf*emb] rows for num score
__device__ float g_aexto[Bd * OPd * 2 * Hd];  // [emb | leaf*emb] rows for op score
__device__ float g_spre[Bd * NTOT + Bd * OPd];

// ---------------- generic GEMM: C = A[RxK] * W[offset slice]^T ----------------
// fused=1: epilogue  out[r] += sum_n v[n]*tanh(acc + Cb[b(r)*H + n])   (atomic)
// fused=0: out[r*H + n] += acc   (atomic; use with grid.z split-K, bias pre-seeded)
__global__ __launch_bounds__(256) void gemm_fused(
    const float* __restrict__ A, int lda,
    const float* __restrict__ W, int ldw, int woff,
    const float* __restrict__ Cb, const float* __restrict__ v,
    float* __restrict__ out, int R, int K, int rows_per_b, int fused)
{
    __shared__ float As[8][128];
    __shared__ float Bs[8][128];
    const int tid = threadIdx.x;
    const int m0 = blockIdx.x * 128;
    const int n0 = blockIdx.y * 128;
    const int kchunk = K / gridDim.z;
    const int ks = blockIdx.z * kchunk;
    const int ke = ks + kchunk;
    const int lr = tid >> 1;              // 0..127
    const int lk = (tid & 1) << 2;        // 0 or 4
    const int tm = (tid >> 4) << 3;       // 0,8,...,120
    const int tn = (tid & 15) << 3;

    float acc[8][8];
#pragma unroll
    for (int i = 0; i < 8; i++)
#pragma unroll
        for (int j = 0; j < 8; j++) acc[i][j] = 0.f;

    const int gr = m0 + lr;
    const bool avalid = gr < R;
    const float* arow = A + (size_t)gr * lda;
    const float* wrow = W + (size_t)(n0 + lr) * ldw + woff;

    for (int k0 = ks; k0 < ke; k0 += 8) {
        float4 av = avalid ? *(const float4*)(arow + k0 + lk)
                           : make_float4(0.f, 0.f, 0.f, 0.f);
        float4 bv = *(const float4*)(wrow + k0 + lk);
        As[lk + 0][lr] = av.x; As[lk + 1][lr] = av.y;
        As[lk + 2][lr] = av.z; As[lk + 3][lr] = av.w;
        Bs[lk + 0][lr] = bv.x; Bs[lk + 1][lr] = bv.y;
        Bs[lk + 2][lr] = bv.z; Bs[lk + 3][lr] = bv.w;
        __syncthreads();
#pragma unroll
        for (int kk = 0; kk < 8; kk++) {
            float a[8], b[8];
            *(float4*)&a[0] = *(const float4*)&As[kk][tm];
            *(float4*)&a[4] = *(const float4*)&As[kk][tm + 4];
            *(float4*)&b[0] = *(const float4*)&Bs[kk][tn];
            *(float4*)&b[4] = *(const float4*)&Bs[kk][tn + 4];
#pragma unroll
            for (int i = 0; i < 8; i++)
#pragma unroll
                for (int j = 0; j < 8; j++)
                    acc[i][j] = fmaf(a[i], b[j], acc[i][j]);
        }
        __syncthreads();
    }

    if (fused) {
#pragma unroll
        for (int i = 0; i < 8; i++) {
            const int r = m0 + tm + i;
            const bool valid = r < R;
            const int bi = valid ? (r / rows_per_b) : 0;
            float p = 0.f;
#pragma unroll
            for (int j = 0; j < 8; j++) {
                const int n = n0 + tn + j;
                p = fmaf(v[n], tanhf(acc[i][j] + Cb[bi * Hd + n]), p);
            }
            p += __shfl_xor_sync(0xffffffffu, p, 8);
            p += __shfl_xor_sync(0xffffffffu, p, 4);
            p += __shfl_xor_sync(0xffffffffu, p, 2);
            p += __shfl_xor_sync(0xffffffffu, p, 1);
            if (valid && (tid & 15) == 0) atomicAdd(&out[r], p);
        }
    } else {
#pragma unroll
        for (int i = 0; i < 8; i++) {
            const int r = m0 + tm + i;
            if (r < R) {
#pragma unroll
                for (int j = 0; j < 8; j++)
                    atomicAdd(&out[(size_t)r * Hd + n0 + tn + j], acc[i][j]);
            }
        }
    }
}

// ---------------- small elementwise kernels ----------------
__global__ void fill_bias_kernel(float* dst, const float* __restrict__ bias, int n) {
    int i = blockIdx.x * blockDim.x + threadIdx.x;
    if (i < n) dst[i] = bias[i & (Hd - 1)];
}
__global__ void fill_scalar_kernel(float* dst, const float* __restrict__ sp, int n) {
    int i = blockIdx.x * blockDim.x + threadIdx.x;
    if (i < n) dst[i] = sp[0];
}
__global__ void fill_zero_kernel(float* dst, int n) {
    int i = blockIdx.x * blockDim.x + threadIdx.x;
    if (i < n) dst[i] = 0.f;
}
__global__ void concat_kernel(float* dst, const float* __restrict__ a,
                              const float* __restrict__ b, int rows) {
    int i = blockIdx.x * blockDim.x + threadIdx.x;
    if (i < rows * 2 * Hd) {
        int r = i >> 11, c = i & (2 * Hd - 1);
        dst[i] = (c < Hd) ? a[r * Hd + c] : b[r * Hd + c - Hd];
    }
}
__global__ void tanh_kernel(const float* __restrict__ src, float* dst, int n) {
    int i = blockIdx.x * blockDim.x + threadIdx.x;
    if (i < n) dst[i] = tanhf(src[i]);
}

// node = where(mask, tanh(pre_r)*sig(pre_rg), tanh(pre_l)*sig(pre_lg))
// left_mask dtype auto-detect: int32 / float32 / byte-bool.
__global__ void node_kernel(const unsigned char* __restrict__ lm, float* o_node) {
    __shared__ int smode;
    if (threadIdx.x == 0) {
        int mode = 0;  // 0=int32, 1=bool8, 2=float32
        bool nonalign = false;
        for (int t = 1; t < 64; t++)
            if ((t & 3) && lm[t]) { nonalign = true; break; }
        if (nonalign) {
            const unsigned int* w = (const unsigned int*)lm;
            bool isf = true;
            for (int t = 0; t < 16; t++) {
                unsigned int x = w[t];
                if (x != 0u && x != 0x3F800000u) { isf = false; break; }
            }
            mode = isf ? 2 : 1;
        }
        smode = mode;
    }
    __syncthreads();
    int i = blockIdx.x * blockDim.x + threadIdx.x;
    if (i >= Bd * Hd) return;
    int b = i >> 10;
    bool m;
    if (smode == 1)      m = lm[b] != 0;
    else if (smode == 2) m = ((const float*)lm)[b] != 0.f;
    else                 m = ((const int*)lm)[b] != 0;
    float lv = tanhf(g_pre[i]) * (1.f / (1.f + expf(-g_pre[Bd * Hd + i])));
    float rv = tanhf(g_pre[2 * Bd * Hd + i]) * (1.f / (1.f + expf(-g_pre[3 * Bd * Hd + i])));
    float nv = m ? rv : lv;
    g_node[i] = nv;
    o_node[i] = nv;
}

__global__ void softmax_kernel(const int* __restrict__ seq_mask) {
    int b = blockIdx.x, s = threadIdx.x;  // 512 threads
    __shared__ float red[Sd];
    float val = g_energy[b * Sd + s];
    if (seq_mask[b * Sd + s] == 0) val = NEGV;
    red[s] = val; __syncthreads();
    for (int off = Sd / 2; off > 0; off >>= 1) {
        if (s < off) red[s] = fmaxf(red[s], red[s + off]);
        __syncthreads();
    }
    float mx = red[0]; __syncthreads();
    float ex = expf(val - mx);
    red[s] = ex; __syncthreads();
    for (int off = Sd / 2; off > 0; off >>= 1) {
        if (s < off) red[s] += red[s + off];
        __syncthreads();
    }
    float inv = 1.f / red[0];
    g_energy[b * Sd + s] = ex * inv;
}

__global__ void ctx_kernel(const float* __restrict__ enc, float* o_ctx) {
    int b = blockIdx.x;
    int h = blockIdx.y * 128 + threadIdx.x;
    __shared__ float aw[Sd];
    for (int i = threadIdx.x; i < Sd; i += 128) aw[i] = g_energy[b * Sd + i];
    __syncthreads();
    const float* ep = enc + (size_t)b * Sd * Hd + h;
    float s0 = 0.f;
#pragma unroll 4
    for (int t = 0; t < Sd; t++) s0 = fmaf(aw[t], ep[(size_t)t * Hd], s0);
    g_ctx[b * Hd + h] = s0;
    o_ctx[b * Hd + h] = s0;
}

__global__ void constnum_kernel(const float* __restrict__ cemb,
                                const float* __restrict__ pades, float* o_cn) {
    int i = blockIdx.x * blockDim.x + threadIdx.x;
    if (i >= Bd * NTOT * Hd) return;
    int h = i & (Hd - 1);
    int rn = i >> 10;
    int n = rn % NTOT, b = rn / NTOT;
    o_cn[i] = (n < NCd) ? cemb[n * Hd + h]
                        : pades[((size_t)b * NNd + (n - NCd)) * Hd + h];
}

__global__ void aextn_kernel(const float* __restrict__ X) {  // X = const_num in d_out
    int i = blockIdx.x * blockDim.x + threadIdx.x;
    if (i >= Bd * NTOT * 2 * Hd) return;
    int c = i & (2 * Hd - 1);
    int r = i >> 11;
    int b = r / NTOT;
    float vv;
    if (c < Hd) vv = X[(size_t)r * Hd + c];
    else { int h = c - Hd; vv = X[(size_t)r * Hd + h] * g_leaf[b * Hd + h]; }
    g_aextn[i] = vv;
}
__global__ void aexto_kernel(const float* __restrict__ ope) {
    int i = blockIdx.x * blockDim.x + threadIdx.x;
    if (i >= Bd * OPd * 2 * Hd) return;
    int c = i & (2 * Hd - 1);
    int r = i >> 11;
    int b = r / OPd, n = r % OPd;
    int h = c & (Hd - 1);
    float e = ope[n * Hd + h];
    g_aexto[i] = (c < Hd) ? e : e * g_leaf[b * Hd + h];
}

__global__ void fin_kernel(const int* __restrict__ mask_nums, float* o_num, float* o_op) {
    int i = blockIdx.x * blockDim.x + threadIdx.x;
    if (i < Bd * NTOT) o_num[i] = mask_nums[i] ? g_spre[i] : NEGV;
    if (i < Bd * OPd)  o_op[i]  = g_spre[Bd * NTOT + i];
}

// ---------------- launch ----------------
extern "C" void kernel_launch(void* const* d_in, const int* in_sizes, int n_in,
                              void* d_out, int out_size)
{
    const float* cur_emb     = (const float*)d_in[0];
    const float* left_childs = (const float*)d_in[1];
    const unsigned char* left_mask = (const unsigned char*)d_in[2];
    const float* enc         = (const float*)d_in[3];
    const float* num_pades   = (const float*)d_in[4];
    const int*   seq_mask    = (const int*)d_in[5];
    const int*   mask_nums   = (const int*)d_in[6];
    const float* cemb        = (const float*)d_in[7];
    const float* opemb       = (const float*)d_in[8];
    const float* Wl   = (const float*)d_in[9];
    const float* bl   = (const float*)d_in[10];
    const float* Wlg  = (const float*)d_in[11];
    const float* blg  = (const float*)d_in[12];
    const float* Wr   = (const float*)d_in[13];
    const float* br   = (const float*)d_in[14];
    const float* Wrg  = (const float*)d_in[15];
    const float* brg  = (const float*)d_in[16];
    const float* Wleaf= (const float*)d_in[17];
    const float* bleaf= (const float*)d_in[18];
    const float* Wa   = (const float*)d_in[19];
    const float* ba   = (const float*)d_in[20];
    const float* Ws   = (const float*)d_in[21];
    const float* bs   = (const float*)d_in[22];
    const float* Wna  = (const float*)d_in[23];
    const float* bna  = (const float*)d_in[24];
    const float* Wns  = (const float*)d_in[25];
    const float* Woa  = (const float*)d_in[26];
    const float* boa  = (const float*)d_in[27];
    const float* Wos  = (const float*)d_in[28];

    float* out   = (float*)d_out;
    float* o_num = out;                   // [64,35]
    float* o_op  = out + 2240;            // [64,5]
    float* o_node= out + 2560;            // [64,1,1024]
    float* o_ctx = out + 68096;           // [64,1,1024]
    float* o_cn  = out + 133632;          // [64,35,1024]
    float* o_ope = out + 2427392;         // [5,1024]

    void* p;
    cudaGetSymbolAddress(&p, g_pre);     float* pre_    = (float*)p;
    cudaGetSymbolAddress(&p, g_lc);      float* lc_     = (float*)p;
    cudaGetSymbolAddress(&p, g_node);    float* node_   = (float*)p;
    cudaGetSymbolAddress(&p, g_cnode);   float* cnode_  = (float*)p;
    cudaGetSymbolAddress(&p, g_energy);  float* energy_ = (float*)p;
    cudaGetSymbolAddress(&p, g_ctx);     float* ctx_    = (float*)p;
    cudaGetSymbolAddress(&p, g_cat);     float* cat_    = (float*)p;
    cudaGetSymbolAddress(&p, g_leafpre); float* leafpre_= (float*)p;
    cudaGetSymbolAddress(&p, g_leaf);    float* leaf_   = (float*)p;
    cudaGetSymbolAddress(&p, g_cnum);    float* cnum_   = (float*)p;
    cudaGetSymbolAddress(&p, g_cop);     float* cop_    = (float*)p;
    cudaGetSymbolAddress(&p, g_aextn);   float* aextn_  = (float*)p;
    cudaGetSymbolAddress(&p, g_aexto);   float* aexto_  = (float*)p;
    cudaGetSymbolAddress(&p, g_spre);    float* spre_   = (float*)p;

    const int BH = Bd * Hd;  // 65536

    // --- node branches ---
    fill_bias_kernel<<<BH / 256, 256>>>(pre_,            bl,  BH);
    fill_bias_kernel<<<BH / 256, 256>>>(pre_ + BH,       blg, BH);
    fill_bias_kernel<<<BH / 256, 256>>>(pre_ + 2 * BH,   br,  BH);
    fill_bias_kernel<<<BH / 256, 256>>>(pre_ + 3 * BH,   brg, BH);
    concat_kernel<<<(Bd * 2 * Hd) / 256, 256>>>(lc_, left_childs, cur_emb, Bd);

    dim3 gsmall(1, 8, 8);
    gemm_fused<<<gsmall, 256>>>(cur_emb, Hd,   Wl,  Hd,   0, nullptr, nullptr, pre_,          Bd, Hd,     0, 0);
    gemm_fused<<<gsmall, 256>>>(cur_emb, Hd,   Wlg, Hd,   0, nullptr, nullptr, pre_ + BH,     Bd, Hd,     0, 0);
    gemm_fused<<<gsmall, 256>>>(lc_,    2*Hd,  Wr,  2*Hd, 0, nullptr, nullptr, pre_ + 2 * BH, Bd, 2 * Hd, 0, 0);
    gemm_fused<<<gsmall, 256>>>(lc_,    2*Hd,  Wrg, 2*Hd, 0, nullptr, nullptr, pre_ + 3 * BH, Bd, 2 * Hd, 0, 0);
    node_kernel<<<BH / 256, 256>>>(left_mask, o_node);

    // --- attention ---
    fill_bias_kernel<<<BH / 256, 256>>>(cnode_, ba, BH);
    gemm_fused<<<gsmall, 256>>>(node_, Hd, Wa, 2 * Hd, 0, nullptr, nullptr, cnode_, Bd, Hd, 0, 0);
    fill_scalar_kernel<<<(Bd * Sd) / 256, 256>>>(energy_, bs, Bd * Sd);
    dim3 gbig(256, 8, 1);  // 32768 rows / 128
    gemm_fused<<<gbig, 256>>>(enc, Hd, Wa, 2 * Hd, Hd, cnode_, Ws, energy_, Bd * Sd, Hd, Sd, 1);
    softmax_kernel<<<Bd, Sd>>>(seq_mask);
    dim3 gctx(Bd, 8);
    ctx_kernel<<<gctx, 128>>>(enc, o_ctx);

    // --- outputs that don't depend on leaf ---
    constnum_kernel<<<(Bd * NTOT * Hd + 255) / 256, 256>>>(cemb, num_pades, o_cn);
    cudaMemcpyAsync(o_ope, opemb, OPd * Hd * sizeof(float), cudaMemcpyDeviceToDevice, 0);

    // --- leaf ---
    concat_kernel<<<(Bd * 2 * Hd) / 256, 256>>>(cat_, node_, ctx_, Bd);
    fill_bias_kernel<<<BH / 256, 256>>>(leafpre_, bleaf, BH);
    gemm_fused<<<gsmall, 256>>>(cat_, 2 * Hd, Wleaf, 2 * Hd, 0, nullptr, nullptr, leafpre_, Bd, 2 * Hd, 0, 0);
    tanh_kernel<<<BH / 256, 256>>>(leafpre_, leaf_, BH);

    // --- per-batch score biases ---
    fill_bias_kernel<<<BH / 256, 256>>>(cnum_, bna, BH);
    gemm_fused<<<gsmall, 256>>>(leaf_, Hd, Wna, 3 * Hd, 0, nullptr, nullptr, cnum_, Bd, Hd, 0, 0);
    fill_bias_kernel<<<BH / 256, 256>>>(cop_, boa, BH);
    gemm_fused<<<gsmall, 256>>>(leaf_, Hd, Woa, 3 * Hd, 0, nullptr, nullptr, cop_, Bd, Hd, 0, 0);

    // --- score heads ---
    aextn_kernel<<<(Bd * NTOT * 2 * Hd + 255) / 256, 256>>>(o_cn);
    aexto_kernel<<<(Bd * OPd * 2 * Hd + 255) / 256, 256>>>(opemb);
    fill_zero_kernel<<<(Bd * (NTOT + OPd) + 255) / 256, 256>>>(spre_, Bd * (NTOT + OPd));
    dim3 gnum((Bd * NTOT + 127) / 128, 8, 1);
    gemm_fused<<<gnum, 256>>>(aextn_, 2 * Hd, Wna, 3 * Hd, Hd, cnum_, Wns, spre_, Bd * NTOT, 2 * Hd, NTOT, 1);
    dim3 gop((Bd * OPd + 127) / 128, 8, 1);
    gemm_fused<<<gop, 256>>>(aexto_, 2 * Hd, Woa, 3 * Hd, Hd, cop_, Wos, spre_ + Bd * NTOT, Bd * OPd, 2 * Hd, OPd, 1);

    fin_kernel<<<(Bd * NTOT + 255) / 256, 256>>>(mask_nums, o_num, o_op);
}

// round 2
// speedup vs baseline: 2.0050x; 2.0050x over previous
#include <cuda_runtime.h>
#include <cuda_bf16.h>
#include <cstdint>

#define Hd 1024
#define Bd 64
#define Sd 512
#define NCd 20
#define NNd 15
#define OPd 5
#define NTOT 35
#define NEGV (-1e12f)

// ---------------- scratch (device globals; no allocation allowed) ----------------
__device__ float g_pre[4 * Bd * Hd];        // preacts: l, lg, r, rg
__device__ float g_lc[Bd * 2 * Hd];         // [left_childs | cur_emb]
__device__ float g_node[Bd * Hd];
__device__ float g_cnode[Bd * Hd];          // Wa[:, :H]*node + ba
__device__ float g_energy[Bd * Sd];         // energies -> attn weights
__device__ float g_cat[Bd * 2 * Hd];        // [node | ctx]
__device__ float g_leafpre[Bd * Hd];
__device__ float g_leaf[Bd * Hd];
__device__ float g_cnum[Bd * Hd];           // Wna[:, :H]*leaf + bna
__device__ float g_cop[Bd * Hd];            // Woa[:, :H]*leaf + boa
__device__ float g_spre[Bd * NTOT + Bd * OPd];

// =================================================================================
// TF32 tensor-core GEMM, fused epilogue:
//   out[r] += sum_n v[n] * tanh(acc[r,n] + Cb[(r/rows_per_b)*Hd + n])
// A modes: 0 plain A[R x lda];  1: A row = [X[r] | X[r]*leaf[b]];  2: same but X row = r%rowmod
// W: row-major [* x ldw], uses columns woff..woff+K-1 of rows n0..n0+127. N is always 1024.
// =================================================================================
#define BM 128
#define BN 128
#define BKt 32
#define PITCH 36

__device__ __forceinline__ uint32_t f2tf32(float f) {
    uint32_t u;
    asm("cvt.rna.tf32.f32 %0, %1;" : "=r"(u) : "f"(f));
    return u;
}

__global__ __launch_bounds__(256) void tf32_gemm_fused(
    const float* __restrict__ A, int lda, int amode, int rowmod,
    const float* __restrict__ leaf,
    const float* __restrict__ W, int ldw, int woff,
    const float* __restrict__ Cb, const float* __restrict__ v,
    float* __restrict__ out, int R, int K, int rows_per_b)
{
    __shared__ __align__(16) uint32_t As[BM * PITCH];
    __shared__ __align__(16) uint32_t Bs[BN * PITCH];

    const int tid = threadIdx.x;
    const int n0 = blockIdx.x * BN;      // x = N blocks (8) -> wave reuses A rows via L2
    const int m0 = blockIdx.y * BM;
    const int warp = tid >> 5, lane = tid & 31;
    const int g = lane >> 2, tig = lane & 3;
    const int wm = (warp >> 1) * 32;     // 4 warp rows of 32
    const int wn = (warp & 1) * 64;      // 2 warp cols of 64

    float acc[2][8][4];
#pragma unroll
    for (int mt = 0; mt < 2; mt++)
#pragma unroll
        for (int nt = 0; nt < 8; nt++)
#pragma unroll
            for (int c = 0; c < 4; c++) acc[mt][nt][c] = 0.f;

    for (int k0 = 0; k0 < K; k0 += BKt) {
        // ---- load A tile (BM x BKt) ----
#pragma unroll
        for (int it = 0; it < 4; it++) {
            int idx = tid + it * 256;
            int r = idx >> 3, c4 = idx & 7;
            int gr = m0 + r, gc = k0 + c4 * 4;
            float4 av = make_float4(0.f, 0.f, 0.f, 0.f);
            if (gr < R) {
                if (amode == 0) {
                    av = *(const float4*)(A + (size_t)gr * lda + gc);
                } else {
                    int xr = (amode == 2) ? (gr % rowmod) : gr;
                    if (gc < Hd) {
                        av = *(const float4*)(A + (size_t)xr * Hd + gc);
                    } else {
                        int h = gc - Hd;
                        int b = gr / rows_per_b;
                        av = *(const float4*)(A + (size_t)xr * Hd + h);
                        float4 lf = *(const float4*)(leaf + (size_t)b * Hd + h);
                        av.x *= lf.x; av.y *= lf.y; av.z *= lf.z; av.w *= lf.w;
                    }
                }
            }
            uint4 uv;
            uv.x = f2tf32(av.x); uv.y = f2tf32(av.y);
            uv.z = f2tf32(av.z); uv.w = f2tf32(av.w);
            *(uint4*)&As[r * PITCH + c4 * 4] = uv;
        }
        // ---- load B tile (BN x BKt) from W rows n0.., cols woff+k0.. ----
#pragma unroll
        for (int it = 0; it < 4; it++) {
            int idx = tid + it * 256;
            int r = idx >> 3, c4 = idx & 7;
            int gc = woff + k0 + c4 * 4;
            float4 bv = *(const float4*)(W + (size_t)(n0 + r) * ldw + gc);
            uint4 uv;
            uv.x = f2tf32(bv.x); uv.y = f2tf32(bv.y);
            uv.z = f2tf32(bv.z); uv.w = f2tf32(bv.w);
            *(uint4*)&Bs[r * PITCH + c4 * 4] = uv;
        }
        __syncthreads();

#pragma unroll
        for (int kk = 0; kk < BKt; kk += 8) {
            uint32_t af[2][4];
#pragma unroll
            for (int mt = 0; mt < 2; mt++) {
                int base = (wm + mt * 16 + g) * PITCH + kk;
                af[mt][0] = As[base + tig];
                af[mt][1] = As[base + 8 * PITCH + tig];
                af[mt][2] = As[base + tig + 4];
                af[mt][3] = As[base + 8 * PITCH + tig + 4];
            }
            uint32_t bf[8][2];
#pragma unroll
            for (int nt = 0; nt < 8; nt++) {
                int base = (wn + nt * 8 + g) * PITCH + kk;
                bf[nt][0] = Bs[base + tig];
                bf[nt][1] = Bs[base + tig + 4];
            }
#pragma unroll
            for (int mt = 0; mt < 2; mt++)
#pragma unroll
                for (int nt = 0; nt < 8; nt++) {
                    asm volatile(
                        "mma.sync.aligned.m16n8k8.row.col.f32.tf32.tf32.f32 "
                        "{%0,%1,%2,%3}, {%4,%5,%6,%7}, {%8,%9}, {%0,%1,%2,%3};"
                        : "+f"(acc[mt][nt][0]), "+f"(acc[mt][nt][1]),
                          "+f"(acc[mt][nt][2]), "+f"(acc[mt][nt][3])
                        : "r"(af[mt][0]), "r"(af[mt][1]), "r"(af[mt][2]), "r"(af[mt][3]),
                          "r"(bf[nt][0]), "r"(bf[nt][1]));
                }
        }
        __syncthreads();
    }

    // ---- fused epilogue: per-row v-weighted tanh reduction ----
#pragma unroll
    for (int mt = 0; mt < 2; mt++) {
        int r0 = m0 + wm + mt * 16 + g;
        int r1 = r0 + 8;
        int bi0 = (r0 < R) ? (r0 / rows_per_b) : 0;
        int bi1 = (r1 < R) ? (r1 / rows_per_b) : 0;
        float p0 = 0.f, p1 = 0.f;
#pragma unroll
        for (int nt = 0; nt < 8; nt++) {
            int n = n0 + wn + nt * 8 + tig * 2;
            float v0 = v[n], v1 = v[n + 1];
            p0 = fmaf(v0, tanhf(acc[mt][nt][0] + Cb[(size_t)bi0 * Hd + n]), p0);
            p0 = fmaf(v1, tanhf(acc[mt][nt][1] + Cb[(size_t)bi0 * Hd + n + 1]), p0);
            p1 = fmaf(v0, tanhf(acc[mt][nt][2] + Cb[(size_t)bi1 * Hd + n]), p1);
            p1 = fmaf(v1, tanhf(acc[mt][nt][3] + Cb[(size_t)bi1 * Hd + n + 1]), p1);
        }
        p0 += __shfl_xor_sync(0xffffffffu, p0, 1);
        p0 += __shfl_xor_sync(0xffffffffu, p0, 2);
        p1 += __shfl_xor_sync(0xffffffffu, p1, 1);
        p1 += __shfl_xor_sync(0xffffffffu, p1, 2);
        if (tig == 0) {
            if (r0 < R) atomicAdd(&out[r0], p0);
            if (r1 < R) atomicAdd(&out[r1], p1);
        }
    }
}

// ---------------- SIMT GEMM for tiny (64-row) layers: out[r*Hd+n] += A·W^T -------
__global__ __launch_bounds__(256) void gemm_small(
    const float* __restrict__ A, int lda,
    const float* __restrict__ W, int ldw,
    float* __restrict__ out, int R, int K)
{
    __shared__ float As[8][128];
    __shared__ float Bs[8][128];
    const int tid = threadIdx.x;
    const int n0 = blockIdx.y * 128;
    const int kchunk = K / gridDim.z;
    const int ks = blockIdx.z * kchunk;
    const int ke = ks + kchunk;
    const int lr = tid >> 1;
    const int lk = (tid & 1) << 2;
    const int tm = (tid >> 4) << 3;
    const int tn = (tid & 15) << 3;

    float acc[8][8];
#pragma unroll
    for (int i = 0; i < 8; i++)
#pragma unroll
        for (int j = 0; j < 8; j++) acc[i][j] = 0.f;

    const bool avalid = lr < R;
    const float* arow = A + (size_t)lr * lda;
    const float* wrow = W + (size_t)(n0 + lr) * ldw;

    for (int k0 = ks; k0 < ke; k0 += 8) {
        float4 av = avalid ? *(const float4*)(arow + k0 + lk)
                           : make_float4(0.f, 0.f, 0.f, 0.f);
        float4 bv = *(const float4*)(wrow + k0 + lk);
        As[lk + 0][lr] = av.x; As[lk + 1][lr] = av.y;
        As[lk + 2][lr] = av.z; As[lk + 3][lr] = av.w;
        Bs[lk + 0][lr] = bv.x; Bs[lk + 1][lr] = bv.y;
        Bs[lk + 2][lr] = bv.z; Bs[lk + 3][lr] = bv.w;
        __syncthreads();
#pragma unroll
        for (int kk = 0; kk < 8; kk++) {
            float a[8], b[8];
            *(float4*)&a[0] = *(const float4*)&As[kk][tm];
            *(float4*)&a[4] = *(const float4*)&As[kk][tm + 4];
            *(float4*)&b[0] = *(const float4*)&Bs[kk][tn];
            *(float4*)&b[4] = *(const float4*)&Bs[kk][tn + 4];
#pragma unroll
            for (int i = 0; i < 8; i++)
#pragma unroll
                for (int j = 0; j < 8; j++)
                    acc[i][j] = fmaf(a[i], b[j], acc[i][j]);
        }
        __syncthreads();
    }
#pragma unroll
    for (int i = 0; i < 8; i++) {
        const int r = tm + i;
        if (r < R) {
#pragma unroll
            for (int j = 0; j < 8; j++)
                atomicAdd(&out[(size_t)r * Hd + n0 + tn + j], acc[i][j]);
        }
    }
}

// ---------------- init: all bias seeds + concats + copies in one launch ----------
__global__ void init_kernel(
    const float* __restrict__ bl, const float* __restrict__ blg,
    const float* __restrict__ br, const float* __restrict__ brg,
    const float* __restrict__ ba, const float* __restrict__ bleaf,
    const float* __restrict__ bna, const float* __restrict__ boa,
    const float* __restrict__ bs,
    const float* __restrict__ left_childs, const float* __restrict__ cur_emb,
    const float* __restrict__ opemb, float* __restrict__ o_ope)
{
    const int BH = Bd * Hd;
    int i = blockIdx.x * blockDim.x + threadIdx.x;
    if (i < 4 * BH) {
        int which = i >> 16;            // i / BH
        int h = i & (Hd - 1);
        const float* bp = (which == 0) ? bl : (which == 1) ? blg : (which == 2) ? br : brg;
        g_pre[i] = bp[h];
        return;
    }
    i -= 4 * BH;
    if (i < BH) { g_cnode[i] = ba[i & (Hd - 1)]; return; }
    i -= BH;
    if (i < BH) { g_leafpre[i] = bleaf[i & (Hd - 1)]; return; }
    i -= BH;
    if (i < BH) { g_cnum[i] = bna[i & (Hd - 1)]; return; }
    i -= BH;
    if (i < BH) { g_cop[i] = boa[i & (Hd - 1)]; return; }
    i -= BH;
    if (i < Bd * Sd) { g_energy[i] = bs[0]; return; }
    i -= Bd * Sd;
    if (i < Bd * (NTOT + OPd)) { g_spre[i] = 0.f; return; }
    i -= Bd * (NTOT + OPd);
    if (i < Bd * 2 * Hd) {
        int r = i >> 11, c = i & (2 * Hd - 1);
        g_lc[i] = (c < Hd) ? left_childs[r * Hd + c] : cur_emb[r * Hd + c - Hd];
        return;
    }
    i -= Bd * 2 * Hd;
    if (i < OPd * Hd) { o_ope[i] = opemb[i]; return; }
}

// node = where(mask, tanh(pre_r)*sig(pre_rg), tanh(pre_l)*sig(pre_lg))
__global__ void node_kernel(const unsigned char* __restrict__ lm, float* o_node) {
    __shared__ int smode;
    if (threadIdx.x == 0) {
        int mode = 0;  // 0=int32, 1=bool8, 2=float32
        bool nonalign = false;
        for (int t = 1; t < 64; t++)
            if ((t & 3) && lm[t]) { nonalign = true; break; }
        if (nonalign) {
            const unsigned int* w = (const unsigned int*)lm;
            bool isf = true;
            for (int t = 0; t < 16; t++) {
                unsigned int x = w[t];
                if (x != 0u && x != 0x3F800000u) { isf = false; break; }
            }
            mode = isf ? 2 : 1;
        }
        smode = mode;
    }
    __syncthreads();
    int i = blockIdx.x * blockDim.x + threadIdx.x;
    if (i >= Bd * Hd) return;
    int b = i >> 10;
    bool m;
    if (smode == 1)      m = lm[b] != 0;
    else if (smode == 2) m = ((const float*)lm)[b] != 0.f;
    else                 m = ((const int*)lm)[b] != 0;
    float lv = tanhf(g_pre[i]) * (1.f / (1.f + expf(-g_pre[Bd * Hd + i])));
    float rv = tanhf(g_pre[2 * Bd * Hd + i]) * (1.f / (1.f + expf(-g_pre[3 * Bd * Hd + i])));
    float nv = m ? rv : lv;
    g_node[i] = nv;
    o_node[i] = nv;
    g_cat[(size_t)b * 2 * Hd + (i & (Hd - 1))] = nv;   // first half of [node|ctx]
}

__global__ void softmax_kernel(const int* __restrict__ seq_mask) {
    int b = blockIdx.x, s = threadIdx.x;  // 512 threads
    __shared__ float red[Sd];
    float val = g_energy[b * Sd + s];
    if (seq_mask[b * Sd + s] == 0) val = NEGV;
    red[s] = val; __syncthreads();
    for (int off = Sd / 2; off > 0; off >>= 1) {
        if (s < off) red[s] = fmaxf(red[s], red[s + off]);
        __syncthreads();
    }
    float mx = red[0]; __syncthreads();
    float ex = expf(val - mx);
    red[s] = ex; __syncthreads();
    for (int off = Sd / 2; off > 0; off >>= 1) {
        if (s < off) red[s] += red[s + off];
        __syncthreads();
    }
    g_energy[b * Sd + s] = ex / red[0];
}

__global__ void ctx_kernel(const float* __restrict__ enc, float* o_ctx) {
    int b = blockIdx.x;
    int h = blockIdx.y * 128 + threadIdx.x;
    __shared__ float aw[Sd];
    for (int i = threadIdx.x; i < Sd; i += 128) aw[i] = g_energy[b * Sd + i];
    __syncthreads();
    const float* ep = enc + (size_t)b * Sd * Hd + h;
    float s0 = 0.f;
#pragma unroll 4
    for (int t = 0; t < Sd; t++) s0 = fmaf(aw[t], ep[(size_t)t * Hd], s0);
    o_ctx[b * Hd + h] = s0;
    g_cat[(size_t)b * 2 * Hd + Hd + h] = s0;           // second half of [node|ctx]
}

__global__ void constnum_kernel(const float* __restrict__ cemb,
                                const float* __restrict__ pades, float* o_cn) {
    int i = blockIdx.x * blockDim.x + threadIdx.x;
    if (i >= Bd * NTOT * Hd) return;
    int h = i & (Hd - 1);
    int rn = i >> 10;
    int n = rn % NTOT, b = rn / NTOT;
    o_cn[i] = (n < NCd) ? cemb[n * Hd + h]
                        : pades[((size_t)b * NNd + (n - NCd)) * Hd + h];
}

__global__ void tanh_kernel(const float* __restrict__ src, float* dst, int n) {
    int i = blockIdx.x * blockDim.x + threadIdx.x;
    if (i < n) dst[i] = tanhf(src[i]);
}

__global__ void fin_kernel(const int* __restrict__ mask_nums, float* o_num, float* o_op) {
    int i = blockIdx.x * blockDim.x + threadIdx.x;
    if (i < Bd * NTOT) o_num[i] = mask_nums[i] ? g_spre[i] : NEGV;
    if (i < Bd * OPd)  o_op[i]  = g_spre[Bd * NTOT + i];
}

// ---------------- launch ----------------
extern "C" void kernel_launch(void* const* d_in, const int* in_sizes, int n_in,
                              void* d_out, int out_size)
{
    const float* cur_emb     = (const float*)d_in[0];
    const float* left_childs = (const float*)d_in[1];
    const unsigned char* left_mask = (const unsigned char*)d_in[2];
    const float* enc         = (const float*)d_in[3];
    const float* num_pades   = (const float*)d_in[4];
    const int*   seq_mask    = (const int*)d_in[5];
    const int*   mask_nums   = (const int*)d_in[6];
    const float* cemb        = (const float*)d_in[7];
    const float* opemb       = (const float*)d_in[8];
    const float* Wl   = (const float*)d_in[9];
    const float* Wlg  = (const float*)d_in[11];
    const float* Wr   = (const float*)d_in[13];
    const float* Wrg  = (const float*)d_in[15];
    const float* Wleaf= (const float*)d_in[17];
    const float* Wa   = (const float*)d_in[19];
    const float* Ws   = (const float*)d_in[21];
    const float* Wna  = (const float*)d_in[23];
    const float* Wns  = (const float*)d_in[25];
    const float* Woa  = (const float*)d_in[26];
    const float* Wos  = (const float*)d_in[28];
    const float* bl   = (const float*)d_in[10];
    const float* blg  = (const float*)d_in[12];
    const float* br   = (const float*)d_in[14];
    const float* brg  = (const float*)d_in[16];
    const float* bleaf= (const float*)d_in[18];
    const float* ba   = (const float*)d_in[20];
    const float* bs   = (const float*)d_in[22];
    const float* bna  = (const float*)d_in[24];
    const float* boa  = (const float*)d_in[27];

    float* out   = (float*)d_out;
    float* o_num = out;                   // [64,35]
    float* o_op  = out + 2240;            // [64,5]
    float* o_node= out + 2560;            // [64,1,1024]
    float* o_ctx = out + 68096;           // [64,1,1024]
    float* o_cn  = out + 133632;          // [64,35,1024]
    float* o_ope = out + 2427392;         // [5,1024]

    void* p;
    cudaGetSymbolAddress(&p, g_pre);     float* pre_    = (float*)p;
    cudaGetSymbolAddress(&p, g_lc);      float* lc_     = (float*)p;
    cudaGetSymbolAddress(&p, g_node);    float* node_   = (float*)p;
    cudaGetSymbolAddress(&p, g_cnode);   float* cnode_  = (float*)p;
    cudaGetSymbolAddress(&p, g_energy);  float* energy_ = (float*)p;
    cudaGetSymbolAddress(&p, g_cat);     float* cat_    = (float*)p;
    cudaGetSymbolAddress(&p, g_leafpre); float* leafpre_= (float*)p;
    cudaGetSymbolAddress(&p, g_leaf);    float* leaf_   = (float*)p;
    cudaGetSymbolAddress(&p, g_cnum);    float* cnum_   = (float*)p;
    cudaGetSymbolAddress(&p, g_cop);     float* cop_    = (float*)p;
    cudaGetSymbolAddress(&p, g_spre);    float* spre_   = (float*)p;

    const int BH = Bd * Hd;

    // 1. seed everything in one launch
    {
        int total = 8 * BH + Bd * Sd + Bd * (NTOT + OPd) + 2 * BH + OPd * Hd;
        init_kernel<<<(total + 255) / 256, 256>>>(bl, blg, br, brg, ba, bleaf, bna, boa,
                                                  bs, left_childs, cur_emb, opemb, o_ope);
    }

    // 2. node preacts (tiny SIMT GEMMs, split-K atomics onto bias-seeded buffers)
    dim3 gsmall(1, 8, 8);
    gemm_small<<<gsmall, 256>>>(cur_emb, Hd,   Wl,  Hd,     pre_,          Bd, Hd);
    gemm_small<<<gsmall, 256>>>(cur_emb, Hd,   Wlg, Hd,     pre_ + BH,     Bd, Hd);
    gemm_small<<<gsmall, 256>>>(lc_,    2*Hd,  Wr,  2*Hd,   pre_ + 2 * BH, Bd, 2 * Hd);
    gemm_small<<<gsmall, 256>>>(lc_,    2*Hd,  Wrg, 2*Hd,   pre_ + 3 * BH, Bd, 2 * Hd);
    node_kernel<<<BH / 256, 256>>>(left_mask, o_node);

    // 3. attention: cnode = ba + Wa1@node ; energies via TF32 fused GEMM
    gemm_small<<<gsmall, 256>>>(node_, Hd, Wa, 2 * Hd, cnode_, Bd, Hd);
    {
        dim3 grid(8, 256);   // x = N-blocks (fast) -> wave reuses enc rows via L2
        tf32_gemm_fused<<<grid, 256>>>(enc, Hd, 0, 0, nullptr,
                                       Wa, 2 * Hd, Hd, cnode_, Ws,
                                       energy_, Bd * Sd, Hd, Sd);
    }
    softmax_kernel<<<Bd, Sd>>>(seq_mask);
    dim3 gctx(Bd, 8);
    ctx_kernel<<<gctx, 128>>>(enc, o_ctx);

    // 4. const_num output (independent)
    constnum_kernel<<<(Bd * NTOT * Hd + 255) / 256, 256>>>(cemb, num_pades, o_cn);

    // 5. leaf
    gemm_small<<<gsmall, 256>>>(cat_, 2 * Hd, Wleaf, 2 * Hd, leafpre_, Bd, 2 * Hd);
    tanh_kernel<<<BH / 256, 256>>>(leafpre_, leaf_, BH);

    // 6. per-batch score biases
    gemm_small<<<gsmall, 256>>>(leaf_, Hd, Wna, 3 * Hd, cnum_, Bd, Hd);
    gemm_small<<<gsmall, 256>>>(leaf_, Hd, Woa, 3 * Hd, cop_,  Bd, Hd);

    // 7. score heads (TF32, A synthesized in loader: [emb | leaf*emb])
    {
        dim3 gnum(8, (Bd * NTOT + BM - 1) / BM);
        tf32_gemm_fused<<<gnum, 256>>>(o_cn, 0, 1, 0, leaf_,
                                       Wna, 3 * Hd, Hd, cnum_, Wns,
                                       spre_, Bd * NTOT, 2 * Hd, NTOT);
        dim3 gop(8, (Bd * OPd + BM - 1) / BM);
        tf32_gemm_fused<<<gop, 256>>>(opemb, 0, 2, OPd, leaf_,
                                      Woa, 3 * Hd, Hd, cop_, Wos,
                                      spre_ + Bd * NTOT, Bd * OPd, 2 * Hd, OPd);
    }

    fin_kernel<<<(Bd * NTOT + 255) / 256, 256>>>(mask_nums, o_num, o_op);
}

// round 3
// speedup vs baseline: 2.2191x; 1.1068x over previous
#include <cuda_runtime.h>
#include <cuda_bf16.h>
#include <cstdint>

#define Hd 1024
#define Bd 64
#define Sd 512
#define NCd 20
#define NNd 15
#define OPd 5
#define NTOT 35
#define NEGV (-1e12f)

// ---------------- scratch (device globals; no allocation allowed) ----------------
__device__ float g_pre[4 * Bd * Hd];        // preacts: l, lg, r, rg
__device__ float g_lc[Bd * 2 * Hd];         // [left_childs | cur_emb]
__device__ float g_node[Bd * Hd];
__device__ float g_cnode[Bd * Hd];          // Wa[:, :H]*node + ba
__device__ float g_energy[Bd * Sd];         // energies -> attn weights
__device__ float g_cat[Bd * 2 * Hd];        // [node | ctx]
__device__ float g_leaf[Bd * Hd];
__device__ float g_cnum[Bd * Hd];           // Wna[:, :H]*leaf + bna
__device__ float g_cop[Bd * Hd];            // Woa[:, :H]*leaf + boa
__device__ float g_spre[Bd * NTOT + Bd * OPd];

// =================================================================================
// Skinny GEMM: out[r, n] = act( bias[n] + sum_k A[r,k] * W[n,k] ),  r in [0,64)
// One warp per output column n; A chunks staged in smem; lanes hold k-partials
// for all 64 rows; butterfly allreduce; direct store (no atomics).
// =================================================================================
struct SkJob {
    const float* A;     // [64 x K], row stride lda
    const float* W;     // row-major, row stride ldw (cols [0,K) used)
    const float* bias;  // [1024]
    float* out;         // [64 x 1024], stride Hd
    int lda, ldw, K, act;  // act: 0 none, 1 tanh
};
struct SkJobs { SkJob j[4]; };

#define SK_CHUNK 128

__global__ __launch_bounds__(256) void skinny_gemm(SkJobs jobs) {
    const SkJob jb = jobs.j[blockIdx.y];
    __shared__ __align__(16) float As[64][SK_CHUNK];   // 32 KB
    const int tid = threadIdx.x, warp = tid >> 5, lane = tid & 31;
    const int n = blockIdx.x * 8 + warp;               // gridDim.x = 128
    const float* wrow = jb.W + (size_t)n * jb.ldw;

    float acc[64];
#pragma unroll
    for (int r = 0; r < 64; r++) acc[r] = 0.f;

    for (int kc = 0; kc < jb.K; kc += SK_CHUNK) {
        __syncthreads();   // guard previous iteration's reads
#pragma unroll
        for (int it = 0; it < 8; it++) {
            int idx = tid + it * 256;      // 0..2047
            int r = idx >> 5, c = idx & 31;
            *(float4*)&As[r][c * 4] =
                *(const float4*)(jb.A + (size_t)r * jb.lda + kc + c * 4);
        }
        __syncthreads();
        float4 w = *(const float4*)(wrow + kc + lane * 4);
#pragma unroll
        for (int r = 0; r < 64; r++) {
            float4 a = *(const float4*)&As[r][lane * 4];
            acc[r] = fmaf(w.x, a.x, acc[r]);
            acc[r] = fmaf(w.y, a.y, acc[r]);
            acc[r] = fmaf(w.z, a.z, acc[r]);
            acc[r] = fmaf(w.w, a.w, acc[r]);
        }
    }
#pragma unroll
    for (int off = 16; off; off >>= 1)
#pragma unroll
        for (int r = 0; r < 64; r++)
            acc[r] += __shfl_xor_sync(0xffffffffu, acc[r], off);

    float bv = jb.bias[n];
    float v0 = acc[lane] + bv;
    float v1 = acc[32 + lane] + bv;
    if (jb.act == 1) { v0 = tanhf(v0); v1 = tanhf(v1); }
    jb.out[(size_t)lane * Hd + n] = v0;
    jb.out[(size_t)(32 + lane) * Hd + n] = v1;
}

// =================================================================================
// TF32 tensor-core GEMM, fused epilogue with register double-buffered tiles:
//   out[r] += sum_n v[n] * tanh(acc[r,n] + Cb[(r/rows_per_b)*Hd + n])
// A modes: 0 plain; 1: A row = [X[r] | X[r]*leaf[b]]; 2: same but X row = r%rowmod
// =================================================================================
#define BM 128
#define BN 128
#define BKt 32
#define PITCH 36

__device__ __forceinline__ uint32_t f2tf32(float f) {
    uint32_t u;
    asm("cvt.rna.tf32.f32 %0, %1;" : "=r"(u) : "f"(f));
    return u;
}

__global__ __launch_bounds__(256) void tf32_gemm_fused(
    const float* __restrict__ A, int lda, int amode, int rowmod,
    const float* __restrict__ leaf,
    const float* __restrict__ W, int ldw, int woff,
    const float* __restrict__ Cb, const float* __restrict__ v,
    float* __restrict__ out, int R, int K, int rows_per_b)
{
    __shared__ __align__(16) uint32_t As[BM * PITCH];
    __shared__ __align__(16) uint32_t Bs[BN * PITCH];

    const int tid = threadIdx.x;
    const int n0 = blockIdx.x * BN;      // x = N blocks (8) -> wave reuses A rows via L2
    const int m0 = blockIdx.y * BM;
    const int warp = tid >> 5, lane = tid & 31;
    const int g = lane >> 2, tig = lane & 3;
    const int wm = (warp >> 1) * 32;
    const int wn = (warp & 1) * 64;

    float acc[2][8][4];
#pragma unroll
    for (int mt = 0; mt < 2; mt++)
#pragma unroll
        for (int nt = 0; nt < 8; nt++)
#pragma unroll
            for (int c = 0; c < 4; c++) acc[mt][nt][c] = 0.f;

    float4 ra[4], rb[4];

    auto load_tiles = [&](int k0) {
#pragma unroll
        for (int it = 0; it < 4; it++) {
            int idx = tid + it * 256;
            int r = idx >> 3, c4 = idx & 7;
            int gr = m0 + r, gc = k0 + c4 * 4;
            float4 av = make_float4(0.f, 0.f, 0.f, 0.f);
            if (gr < R) {
                if (amode == 0) {
                    av = *(const float4*)(A + (size_t)gr * lda + gc);
                } else {
                    int xr = (amode == 2) ? (gr % rowmod) : gr;
                    if (gc < Hd) {
                        av = *(const float4*)(A + (size_t)xr * Hd + gc);
                    } else {
                        int h = gc - Hd;
                        int b = gr / rows_per_b;
                        av = *(const float4*)(A + (size_t)xr * Hd + h);
                        float4 lf = *(const float4*)(leaf + (size_t)b * Hd + h);
                        av.x *= lf.x; av.y *= lf.y; av.z *= lf.z; av.w *= lf.w;
                    }
                }
            }
            ra[it] = av;
            float4 bv = *(const float4*)(W + (size_t)(n0 + r) * ldw + woff + gc);
            rb[it] = bv;
        }
    };
    auto store_tiles = [&]() {
#pragma unroll
        for (int it = 0; it < 4; it++) {
            int idx = tid + it * 256;
            int r = idx >> 3, c4 = idx & 7;
            uint4 ua, ub;
            ua.x = f2tf32(ra[it].x); ua.y = f2tf32(ra[it].y);
            ua.z = f2tf32(ra[it].z); ua.w = f2tf32(ra[it].w);
            ub.x = f2tf32(rb[it].x); ub.y = f2tf32(rb[it].y);
            ub.z = f2tf32(rb[it].z); ub.w = f2tf32(rb[it].w);
            *(uint4*)&As[r * PITCH + c4 * 4] = ua;
            *(uint4*)&Bs[r * PITCH + c4 * 4] = ub;
        }
    };

    load_tiles(0);
    for (int k0 = 0; k0 < K; k0 += BKt) {
        store_tiles();
        __syncthreads();
        if (k0 + BKt < K) load_tiles(k0 + BKt);   // prefetch in flight during mma

#pragma unroll
        for (int kk = 0; kk < BKt; kk += 8) {
            uint32_t af[2][4];
#pragma unroll
            for (int mt = 0; mt < 2; mt++) {
                int base = (wm + mt * 16 + g) * PITCH + kk;
                af[mt][0] = As[base + tig];
                af[mt][1] = As[base + 8 * PITCH + tig];
                af[mt][2] = As[base + tig + 4];
                af[mt][3] = As[base + 8 * PITCH + tig + 4];
            }
            uint32_t bf[8][2];
#pragma unroll
            for (int nt = 0; nt < 8; nt++) {
                int base = (wn + nt * 8 + g) * PITCH + kk;
                bf[nt][0] = Bs[base + tig];
                bf[nt][1] = Bs[base + tig + 4];
            }
#pragma unroll
            for (int mt = 0; mt < 2; mt++)
#pragma unroll
                for (int nt = 0; nt < 8; nt++) {
                    asm volatile(
                        "mma.sync.aligned.m16n8k8.row.col.f32.tf32.tf32.f32 "
                        "{%0,%1,%2,%3}, {%4,%5,%6,%7}, {%8,%9}, {%0,%1,%2,%3};"
                        : "+f"(acc[mt][nt][0]), "+f"(acc[mt][nt][1]),
                          "+f"(acc[mt][nt][2]), "+f"(acc[mt][nt][3])
                        : "r"(af[mt][0]), "r"(af[mt][1]), "r"(af[mt][2]), "r"(af[mt][3]),
                          "r"(bf[nt][0]), "r"(bf[nt][1]));
                }
        }
        __syncthreads();
    }

    // fused epilogue: per-row v-weighted tanh reduction
#pragma unroll
    for (int mt = 0; mt < 2; mt++) {
        int r0 = m0 + wm + mt * 16 + g;
        int r1 = r0 + 8;
        int bi0 = (r0 < R) ? (r0 / rows_per_b) : 0;
        int bi1 = (r1 < R) ? (r1 / rows_per_b) : 0;
        float p0 = 0.f, p1 = 0.f;
#pragma unroll
        for (int nt = 0; nt < 8; nt++) {
            int n = n0 + wn + nt * 8 + tig * 2;
            float v0 = v[n], v1 = v[n + 1];
            p0 = fmaf(v0, tanhf(acc[mt][nt][0] + Cb[(size_t)bi0 * Hd + n]), p0);
            p0 = fmaf(v1, tanhf(acc[mt][nt][1] + Cb[(size_t)bi0 * Hd + n + 1]), p0);
            p1 = fmaf(v0, tanhf(acc[mt][nt][2] + Cb[(size_t)bi1 * Hd + n]), p1);
            p1 = fmaf(v1, tanhf(acc[mt][nt][3] + Cb[(size_t)bi1 * Hd + n + 1]), p1);
        }
        p0 += __shfl_xor_sync(0xffffffffu, p0, 1);
        p0 += __shfl_xor_sync(0xffffffffu, p0, 2);
        p1 += __shfl_xor_sync(0xffffffffu, p1, 1);
        p1 += __shfl_xor_sync(0xffffffffu, p1, 2);
        if (tig == 0) {
            if (r0 < R) atomicAdd(&out[r0], p0);
            if (r1 < R) atomicAdd(&out[r1], p1);
        }
    }
}

// ---------------- init: energy seed + spre zero + lc concat ----------------
__global__ void init_kernel(const float* __restrict__ bs,
                            const float* __restrict__ left_childs,
                            const float* __restrict__ cur_emb)
{
    int i = blockIdx.x * blockDim.x + threadIdx.x;
    if (i < Bd * Sd) { g_energy[i] = bs[0]; return; }
    i -= Bd * Sd;
    if (i < Bd * (NTOT + OPd)) { g_spre[i] = 0.f; return; }
    i -= Bd * (NTOT + OPd);
    if (i < Bd * 2 * Hd) {
        int r = i >> 11, c = i & (2 * Hd - 1);
        g_lc[i] = (c < Hd) ? left_childs[r * Hd + c] : cur_emb[r * Hd + c - Hd];
    }
}

// node = where(mask, tanh(pre_r)*sig(pre_rg), tanh(pre_l)*sig(pre_lg))
__global__ void node_kernel(const unsigned char* __restrict__ lm, float* o_node) {
    __shared__ int smode;
    if (threadIdx.x == 0) {
        int mode = 0;  // 0=int32, 1=bool8, 2=float32
        bool nonalign = false;
        for (int t = 1; t < 64; t++)
            if ((t & 3) && lm[t]) { nonalign = true; break; }
        if (nonalign) {
            const unsigned int* w = (const unsigned int*)lm;
            bool isf = true;
            for (int t = 0; t < 16; t++) {
                unsigned int x = w[t];
                if (x != 0u && x != 0x3F800000u) { isf = false; break; }
            }
            mode = isf ? 2 : 1;
        }
        smode = mode;
    }
    __syncthreads();
    int i = blockIdx.x * blockDim.x + threadIdx.x;
    if (i >= Bd * Hd) return;
    int b = i >> 10;
    bool m;
    if (smode == 1)      m = lm[b] != 0;
    else if (smode == 2) m = ((const float*)lm)[b] != 0.f;
    else                 m = ((const int*)lm)[b] != 0;
    float lv = tanhf(g_pre[i]) * (1.f / (1.f + expf(-g_pre[Bd * Hd + i])));
    float rv = tanhf(g_pre[2 * Bd * Hd + i]) * (1.f / (1.f + expf(-g_pre[3 * Bd * Hd + i])));
    float nv = m ? rv : lv;
    g_node[i] = nv;
    o_node[i] = nv;
    g_cat[(size_t)b * 2 * Hd + (i & (Hd - 1))] = nv;
}

__global__ void softmax_kernel(const int* __restrict__ seq_mask) {
    int b = blockIdx.x, s = threadIdx.x;
    __shared__ float red[Sd];
    float val = g_energy[b * Sd + s];
    if (seq_mask[b * Sd + s] == 0) val = NEGV;
    red[s] = val; __syncthreads();
    for (int off = Sd / 2; off > 0; off >>= 1) {
        if (s < off) red[s] = fmaxf(red[s], red[s + off]);
        __syncthreads();
    }
    float mx = red[0]; __syncthreads();
    float ex = expf(val - mx);
    red[s] = ex; __syncthreads();
    for (int off = Sd / 2; off > 0; off >>= 1) {
        if (s < off) red[s] += red[s + off];
        __syncthreads();
    }
    g_energy[b * Sd + s] = ex / red[0];
}

__global__ void ctx_kernel(const float* __restrict__ enc, float* o_ctx) {
    int b = blockIdx.x;
    int h = blockIdx.y * 128 + threadIdx.x;
    __shared__ float aw[Sd];
    for (int i = threadIdx.x; i < Sd; i += 128) aw[i] = g_energy[b * Sd + i];
    __syncthreads();
    const float* ep = enc + (size_t)b * Sd * Hd + h;
    float s0 = 0.f;
#pragma unroll 4
    for (int t = 0; t < Sd; t++) s0 = fmaf(aw[t], ep[(size_t)t * Hd], s0);
    o_ctx[b * Hd + h] = s0;
    g_cat[(size_t)b * 2 * Hd + Hd + h] = s0;
}

__global__ void constnum_kernel(const float* __restrict__ cemb,
                                const float* __restrict__ pades, float* o_cn) {
    int i = blockIdx.x * blockDim.x + threadIdx.x;
    if (i >= Bd * NTOT * Hd) return;
    int h = i & (Hd - 1);
    int rn = i >> 10;
    int n = rn % NTOT, b = rn / NTOT;
    o_cn[i] = (n < NCd) ? cemb[n * Hd + h]
                        : pades[((size_t)b * NNd + (n - NCd)) * Hd + h];
}

__global__ void fin_kernel(const int* __restrict__ mask_nums, float* o_num, float* o_op) {
    int i = blockIdx.x * blockDim.x + threadIdx.x;
    if (i < Bd * NTOT) o_num[i] = mask_nums[i] ? g_spre[i] : NEGV;
    if (i < Bd * OPd)  o_op[i]  = g_spre[Bd * NTOT + i];
}

// ---------------- launch ----------------
extern "C" void kernel_launch(void* const* d_in, const int* in_sizes, int n_in,
                              void* d_out, int out_size)
{
    const float* cur_emb     = (const float*)d_in[0];
    const float* left_childs = (const float*)d_in[1];
    const unsigned char* left_mask = (const unsigned char*)d_in[2];
    const float* enc         = (const float*)d_in[3];
    const float* num_pades   = (const float*)d_in[4];
    const int*   seq_mask    = (const int*)d_in[5];
    const int*   mask_nums   = (const int*)d_in[6];
    const float* cemb        = (const float*)d_in[7];
    const float* opemb       = (const float*)d_in[8];
    const float* Wl   = (const float*)d_in[9];
    const float* bl   = (const float*)d_in[10];
    const float* Wlg  = (const float*)d_in[11];
    const float* blg  = (const float*)d_in[12];
    const float* Wr   = (const float*)d_in[13];
    const float* br   = (const float*)d_in[14];
    const float* Wrg  = (const float*)d_in[15];
    const float* brg  = (const float*)d_in[16];
    const float* Wleaf= (const float*)d_in[17];
    const float* bleaf= (const float*)d_in[18];
    const float* Wa   = (const float*)d_in[19];
    const float* ba   = (const float*)d_in[20];
    const float* Ws   = (const float*)d_in[21];
    const float* bs   = (const float*)d_in[22];
    const float* Wna  = (const float*)d_in[23];
    const float* bna  = (const float*)d_in[24];
    const float* Wns  = (const float*)d_in[25];
    const float* Woa  = (const float*)d_in[26];
    const float* boa  = (const float*)d_in[27];
    const float* Wos  = (const float*)d_in[28];

    float* out   = (float*)d_out;
    float* o_num = out;                   // [64,35]
    float* o_op  = out + 2240;            // [64,5]
    float* o_node= out + 2560;            // [64,1,1024]
    float* o_ctx = out + 68096;           // [64,1,1024]
    float* o_cn  = out + 133632;          // [64,35,1024]
    float* o_ope = out + 2427392;         // [5,1024]

    void* p;
    cudaGetSymbolAddress(&p, g_pre);     float* pre_    = (float*)p;
    cudaGetSymbolAddress(&p, g_lc);      float* lc_     = (float*)p;
    cudaGetSymbolAddress(&p, g_node);    float* node_   = (float*)p;
    cudaGetSymbolAddress(&p, g_cnode);   float* cnode_  = (float*)p;
    cudaGetSymbolAddress(&p, g_energy);  float* energy_ = (float*)p;
    cudaGetSymbolAddress(&p, g_cat);     float* cat_    = (float*)p;
    cudaGetSymbolAddress(&p, g_leaf);    float* leaf_   = (float*)p;
    cudaGetSymbolAddress(&p, g_cnum);    float* cnum_   = (float*)p;
    cudaGetSymbolAddress(&p, g_cop);     float* cop_    = (float*)p;
    cudaGetSymbolAddress(&p, g_spre);    float* spre_   = (float*)p;

    const int BH = Bd * Hd;

    // 1. init (energy/spre/lc)  + o_ope copy
    {
        int total = Bd * Sd + Bd * (NTOT + OPd) + 2 * BH;
        init_kernel<<<(total + 255) / 256, 256>>>(bs, left_childs, cur_emb);
    }
    cudaMemcpyAsync(o_ope, opemb, OPd * Hd * sizeof(float), cudaMemcpyDeviceToDevice, 0);

    // 2. node preacts: 4 skinny jobs in one launch
    {
        SkJobs js;
        js.j[0] = { cur_emb, Wl,  bl,  pre_,           Hd,     Hd,     Hd,     0 };
        js.j[1] = { cur_emb, Wlg, blg, pre_ + BH,      Hd,     Hd,     Hd,     0 };
        js.j[2] = { lc_,     Wr,  br,  pre_ + 2 * BH,  2 * Hd, 2 * Hd, 2 * Hd, 0 };
        js.j[3] = { lc_,     Wrg, brg, pre_ + 3 * BH,  2 * Hd, 2 * Hd, 2 * Hd, 0 };
        skinny_gemm<<<dim3(128, 4), 256>>>(js);
    }
    node_kernel<<<BH / 256, 256>>>(left_mask, o_node);

    // 3. cnode = ba + Wa[:, :H] @ node
    {
        SkJobs js;
        js.j[0] = { node_, Wa, ba, cnode_, Hd, 2 * Hd, Hd, 0 };
        skinny_gemm<<<dim3(128, 1), 256>>>(js);
    }

    // 4. const_num output (independent; placed here so big GEMM is launch #6 for ncu)
    constnum_kernel<<<(Bd * NTOT * Hd + 255) / 256, 256>>>(cemb, num_pades, o_cn);

    // 5. attention energies via TF32 fused GEMM (launch #6)
    {
        dim3 grid(8, 256);
        tf32_gemm_fused<<<grid, 256>>>(enc, Hd, 0, 0, nullptr,
                                       Wa, 2 * Hd, Hd, cnode_, Ws,
                                       energy_, Bd * Sd, Hd, Sd);
    }
    softmax_kernel<<<Bd, Sd>>>(seq_mask);
    dim3 gctx(Bd, 8);
    ctx_kernel<<<gctx, 128>>>(enc, o_ctx);

    // 6. leaf = tanh(Wleaf @ [node|ctx] + bleaf)   (tanh fused)
    {
        SkJobs js;
        js.j[0] = { cat_, Wleaf, bleaf, leaf_, 2 * Hd, 2 * Hd, 2 * Hd, 1 };
        skinny_gemm<<<dim3(128, 1), 256>>>(js);
    }

    // 7. per-batch score biases (2 jobs, one launch)
    {
        SkJobs js;
        js.j[0] = { leaf_, Wna, bna, cnum_, Hd, 3 * Hd, Hd, 0 };
        js.j[1] = { leaf_, Woa, boa, cop_,  Hd, 3 * Hd, Hd, 0 };
        skinny_gemm<<<dim3(128, 2), 256>>>(js);
    }

    // 8. score heads (TF32, A synthesized in loader: [emb | leaf*emb])
    {
        dim3 gnum(8, (Bd * NTOT + BM - 1) / BM);
        tf32_gemm_fused<<<gnum, 256>>>(o_cn, 0, 1, 0, leaf_,
                                       Wna, 3 * Hd, Hd, cnum_, Wns,
                                       spre_, Bd * NTOT, 2 * Hd, NTOT);
        dim3 gop(8, (Bd * OPd + BM - 1) / BM);
        tf32_gemm_fused<<<gop, 256>>>(opemb, 0, 2, OPd, leaf_,
                                      Woa, 3 * Hd, Hd, cop_, Wos,
                                      spre_ + Bd * NTOT, Bd * OPd, 2 * Hd, OPd);
    }

    fin_kernel<<<(Bd * NTOT + 255) / 256, 256>>>(mask_nums, o_num, o_op);
}

// round 5
// speedup vs baseline: 2.2834x; 1.0290x over previous
#include <cuda_runtime.h>
#include <cuda_bf16.h>
#include <cstdint>

#define Hd 1024
#define Bd 64
#define Sd 512
#define NCd 20
#define NNd 15
#define OPd 5
#define NTOT 35
#define NEGV (-1e12f)

// ---------------- scratch (device globals; no allocation allowed) ----------------
__device__ float g_pre[4 * Bd * Hd];
__device__ float g_lc[Bd * 2 * Hd];
__device__ float g_node[Bd * Hd];
__device__ float g_cnode[Bd * Hd];
__device__ float g_energy[Bd * Sd];
__device__ float g_cat[Bd * 2 * Hd];
__device__ float g_leaf[Bd * Hd];
__device__ float g_cnum[Bd * Hd];
__device__ float g_cop[Bd * Hd];
__device__ float g_spre[Bd * NTOT + Bd * OPd];

// ================= helpers =================
__device__ __forceinline__ uint32_t smem_u32(const void* p) {
    uint32_t a;
    asm("{ .reg .u64 t; cvta.to.shared.u64 t, %1; cvt.u32.u64 %0, t; }" : "=r"(a) : "l"(p));
    return a;
}
__device__ __forceinline__ uint32_t f2tf32(float f) {
    uint32_t u;
    asm("cvt.rna.tf32.f32 %0, %1;" : "=r"(u) : "f"(f));
    return u;
}
__device__ __forceinline__ void cpasync16(uint32_t saddr, const void* g) {
    asm volatile("cp.async.cg.shared.global [%0], [%1], 16;" :: "r"(saddr), "l"(g));
}
#define CP_COMMIT() asm volatile("cp.async.commit_group;" ::: "memory")
#define CP_WAIT1()  asm volatile("cp.async.wait_group 1;" ::: "memory")
#define CP_WAIT0()  asm volatile("cp.async.wait_group 0;" ::: "memory")

// =================================================================================
// cp.async double-buffered mma.sync TF32 energies GEMM
//   D[32768 x 1024] = enc @ Wa[:, Hd:2Hd]^T;  out[row] += sum_n Ws[n]*tanh(D+Cb)
//   CTA tile 128x256, warp tile 64x64 (8 warps, 2x4), BK=32, 2-stage cp.async.
// =================================================================================
#define EBM 128
#define EBN 256
#define EBK 32
#define EPITCH 36
#define ESTAGE ((EBM + EBN) * EPITCH)          // floats per stage: 13824
#define ESMEM  (2 * ESTAGE * 4)                // 110592 bytes

__global__ __launch_bounds__(256) void mma_energy_gemm(
    const float* __restrict__ enc, const float* __restrict__ W,
    const float* __restrict__ Cb, const float* __restrict__ v,
    float* __restrict__ outp)
{
    extern __shared__ __align__(16) float esm[];
    const int tid = threadIdx.x;
    const int n0 = blockIdx.x * EBN;
    const int m0 = blockIdx.y * EBM;
    const int warp = tid >> 5, lane = tid & 31;
    const int g = lane >> 2, tig = lane & 3;
    const int wm = (warp >> 2) * 64;    // 2 warp-rows of 64
    const int wn = (warp & 3) * 64;     // 4 warp-cols of 64

    const uint32_t sbase = smem_u32(esm);
    const uint32_t sA[2] = { sbase, sbase + (uint32_t)ESTAGE * 4 };
    const uint32_t sB[2] = { sbase + EBM * EPITCH * 4,
                             sbase + (uint32_t)ESTAGE * 4 + EBM * EPITCH * 4 };

    float acc[4][8][4];
#pragma unroll
    for (int mt = 0; mt < 4; mt++)
#pragma unroll
        for (int nt = 0; nt < 8; nt++)
#pragma unroll
            for (int c = 0; c < 4; c++) acc[mt][nt][c] = 0.f;

    const int ar = tid >> 3, ac4 = tid & 7;          // A loader: row 0..31 step, col-chunk
    const float* agp = enc + (size_t)(m0 + ar) * Hd + ac4 * 4;
    const float* bgp = W + (size_t)(n0 + ar) * (2 * Hd) + Hd + ac4 * 4;

#define EPREFETCH(c_) do {                                                       \
    const int _b = (c_) & 1;                                                     \
    const int _k0 = (c_) * EBK;                                                  \
    _Pragma("unroll")                                                            \
    for (int it = 0; it < 4; it++)                                               \
        cpasync16(sA[_b] + (uint32_t)(((ar + it * 32) * EPITCH + ac4 * 4) * 4),  \
                  agp + (size_t)(it * 32) * Hd + _k0);                           \
    _Pragma("unroll")                                                            \
    for (int it = 0; it < 8; it++)                                               \
        cpasync16(sB[_b] + (uint32_t)(((ar + it * 32) * EPITCH + ac4 * 4) * 4),  \
                  bgp + (size_t)(it * 32) * (2 * Hd) + _k0);                     \
    CP_COMMIT();                                                                 \
} while (0)

    EPREFETCH(0);
    EPREFETCH(1);

    const int NIT = Hd / EBK;   // 32
    for (int c = 0; c < NIT; c++) {
        const int b = c & 1;
        if (c + 1 < NIT) CP_WAIT1(); else CP_WAIT0();
        __syncthreads();

        const uint32_t* Au = (const uint32_t*)(esm + (b ? ESTAGE : 0));
        const uint32_t* Bu = (const uint32_t*)(esm + (b ? ESTAGE : 0) + EBM * EPITCH);

#pragma unroll
        for (int kk = 0; kk < EBK; kk += 8) {
            uint32_t af[4][4];
#pragma unroll
            for (int mt = 0; mt < 4; mt++) {
                int base = (wm + mt * 16 + g) * EPITCH + kk;
                af[mt][0] = Au[base + tig];
                af[mt][1] = Au[base + 8 * EPITCH + tig];
                af[mt][2] = Au[base + tig + 4];
                af[mt][3] = Au[base + 8 * EPITCH + tig + 4];
            }
            uint32_t bf[8][2];
#pragma unroll
            for (int nt = 0; nt < 8; nt++) {
                int base = (wn + nt * 8 + g) * EPITCH + kk;
                bf[nt][0] = Bu[base + tig];
                bf[nt][1] = Bu[base + tig + 4];
            }
#pragma unroll
            for (int mt = 0; mt < 4; mt++)
#pragma unroll
                for (int nt = 0; nt < 8; nt++) {
                    asm volatile(
                        "mma.sync.aligned.m16n8k8.row.col.f32.tf32.tf32.f32 "
                        "{%0,%1,%2,%3}, {%4,%5,%6,%7}, {%8,%9}, {%0,%1,%2,%3};"
                        : "+f"(acc[mt][nt][0]), "+f"(acc[mt][nt][1]),
                          "+f"(acc[mt][nt][2]), "+f"(acc[mt][nt][3])
                        : "r"(af[mt][0]), "r"(af[mt][1]), "r"(af[mt][2]), "r"(af[mt][3]),
                          "r"(bf[nt][0]), "r"(bf[nt][1]));
                }
        }
        __syncthreads();
        if (c + 2 < NIT) EPREFETCH(c + 2);
    }

    // fused epilogue: per-row Ws-weighted tanh reduction (rows all valid: R=32768)
#pragma unroll
    for (int mt = 0; mt < 4; mt++) {
        const int r0 = m0 + wm + mt * 16 + g;
        const int r1 = r0 + 8;
        const int bi0 = r0 >> 9;   // row / Sd
        const int bi1 = r1 >> 9;
        float p0 = 0.f, p1 = 0.f;
#pragma unroll
        for (int nt = 0; nt < 8; nt++) {
            const int n = n0 + wn + nt * 8 + tig * 2;
            const float v0 = v[n], v1 = v[n + 1];
            p0 = fmaf(v0, tanhf(acc[mt][nt][0] + Cb[(size_t)bi0 * Hd + n]), p0);
            p0 = fmaf(v1, tanhf(acc[mt][nt][1] + Cb[(size_t)bi0 * Hd + n + 1]), p0);
            p1 = fmaf(v0, tanhf(acc[mt][nt][2] + Cb[(size_t)bi1 * Hd + n]), p1);
            p1 = fmaf(v1, tanhf(acc[mt][nt][3] + Cb[(size_t)bi1 * Hd + n + 1]), p1);
        }
        p0 += __shfl_xor_sync(0xffffffffu, p0, 1);
        p0 += __shfl_xor_sync(0xffffffffu, p0, 2);
        p1 += __shfl_xor_sync(0xffffffffu, p1, 1);
        p1 += __shfl_xor_sync(0xffffffffu, p1, 2);
        if (tig == 0) {
            atomicAdd(&outp[r0], p0);
            atomicAdd(&outp[r1], p1);
        }
    }
}

// =================================================================================
// Skinny GEMM: one warp per output column (unchanged)
// =================================================================================
struct SkJob {
    const float* A;
    const float* W;
    const float* bias;
    float* out;
    int lda, ldw, K, act;
};
struct SkJobs { SkJob j[4]; };

#define SK_CHUNK 128

__global__ __launch_bounds__(256) void skinny_gemm(SkJobs jobs) {
    const SkJob jb = jobs.j[blockIdx.y];
    __shared__ __align__(16) float As[64][SK_CHUNK];
    const int tid = threadIdx.x, warp = tid >> 5, lane = tid & 31;
    const int n = blockIdx.x * 8 + warp;
    const float* wrow = jb.W + (size_t)n * jb.ldw;

    float acc[64];
#pragma unroll
    for (int r = 0; r < 64; r++) acc[r] = 0.f;

    for (int kc = 0; kc < jb.K; kc += SK_CHUNK) {
        __syncthreads();
#pragma unroll
        for (int it = 0; it < 8; it++) {
            int idx = tid + it * 256;
            int r = idx >> 5, c = idx & 31;
            *(float4*)&As[r][c * 4] =
                *(const float4*)(jb.A + (size_t)r * jb.lda + kc + c * 4);
        }
        __syncthreads();
        float4 w = *(const float4*)(wrow + kc + lane * 4);
#pragma unroll
        for (int r = 0; r < 64; r++) {
            float4 a = *(const float4*)&As[r][lane * 4];
            acc[r] = fmaf(w.x, a.x, acc[r]);
            acc[r] = fmaf(w.y, a.y, acc[r]);
            acc[r] = fmaf(w.z, a.z, acc[r]);
            acc[r] = fmaf(w.w, a.w, acc[r]);
        }
    }
#pragma unroll
    for (int off = 16; off; off >>= 1)
#pragma unroll
        for (int r = 0; r < 64; r++)
            acc[r] += __shfl_xor_sync(0xffffffffu, acc[r], off);

    float bv = jb.bias[n];
    float v0 = acc[lane] + bv;
    float v1 = acc[32 + lane] + bv;
    if (jb.act == 1) { v0 = tanhf(v0); v1 = tanhf(v1); }
    jb.out[(size_t)lane * Hd + n] = v0;
    jb.out[(size_t)(32 + lane) * Hd + n] = v1;
}

// =================================================================================
// mma.sync TF32 fused GEMM (score heads)
// =================================================================================
#define BM 128
#define BN 128
#define BKt 32
#define PITCH 36

__global__ __launch_bounds__(256) void tf32_gemm_fused(
    const float* __restrict__ A, int lda, int amode, int rowmod,
    const float* __restrict__ leaf,
    const float* __restrict__ W, int ldw, int woff,
    const float* __restrict__ Cb, const float* __restrict__ v,
    float* __restrict__ out, int R, int K, int rows_per_b)
{
    __shared__ __align__(16) uint32_t As[BM * PITCH];
    __shared__ __align__(16) uint32_t Bs[BN * PITCH];

    const int tid = threadIdx.x;
    const int n0 = blockIdx.x * BN;
    const int m0 = blockIdx.y * BM;
    const int warp = tid >> 5, lane = tid & 31;
    const int g = lane >> 2, tig = lane & 3;
    const int wm = (warp >> 1) * 32;
    const int wn = (warp & 1) * 64;

    float acc[2][8][4];
#pragma unroll
    for (int mt = 0; mt < 2; mt++)
#pragma unroll
        for (int nt = 0; nt < 8; nt++)
#pragma unroll
            for (int c = 0; c < 4; c++) acc[mt][nt][c] = 0.f;

    for (int k0 = 0; k0 < K; k0 += BKt) {
#pragma unroll
        for (int it = 0; it < 4; it++) {
            int idx = tid + it * 256;
            int r = idx >> 3, c4 = idx & 7;
            int gr = m0 + r, gc = k0 + c4 * 4;
            float4 av = make_float4(0.f, 0.f, 0.f, 0.f);
            if (gr < R) {
                if (amode == 0) {
                    av = *(const float4*)(A + (size_t)gr * lda + gc);
                } else {
                    int xr = (amode == 2) ? (gr % rowmod) : gr;
                    if (gc < Hd) {
                        av = *(const float4*)(A + (size_t)xr * Hd + gc);
                    } else {
                        int h = gc - Hd;
                        int b = gr / rows_per_b;
                        av = *(const float4*)(A + (size_t)xr * Hd + h);
                        float4 lf = *(const float4*)(leaf + (size_t)b * Hd + h);
                        av.x *= lf.x; av.y *= lf.y; av.z *= lf.z; av.w *= lf.w;
                    }
                }
            }
            float4 bv = *(const float4*)(W + (size_t)(n0 + r) * ldw + woff + gc);
            uint4 ua, ub;
            ua.x = f2tf32(av.x); ua.y = f2tf32(av.y);
            ua.z = f2tf32(av.z); ua.w = f2tf32(av.w);
            ub.x = f2tf32(bv.x); ub.y = f2tf32(bv.y);
            ub.z = f2tf32(bv.z); ub.w = f2tf32(bv.w);
            *(uint4*)&As[r * PITCH + c4 * 4] = ua;
            *(uint4*)&Bs[r * PITCH + c4 * 4] = ub;
        }
        __syncthreads();

#pragma unroll
        for (int kk = 0; kk < BKt; kk += 8) {
            uint32_t af[2][4];
#pragma unroll
            for (int mt = 0; mt < 2; mt++) {
                int base = (wm + mt * 16 + g) * PITCH + kk;
                af[mt][0] = As[base + tig];
                af[mt][1] = As[base + 8 * PITCH + tig];
                af[mt][2] = As[base + tig + 4];
                af[mt][3] = As[base + 8 * PITCH + tig + 4];
            }
            uint32_t bf[8][2];
#pragma unroll
            for (int nt = 0; nt < 8; nt++) {
                int base = (wn + nt * 8 + g) * PITCH + kk;
                bf[nt][0] = Bs[base + tig];
                bf[nt][1] = Bs[base + tig + 4];
            }
#pragma unroll
            for (int mt = 0; mt < 2; mt++)
#pragma unroll
                for (int nt = 0; nt < 8; nt++) {
                    asm volatile(
                        "mma.sync.aligned.m16n8k8.row.col.f32.tf32.tf32.f32 "
                        "{%0,%1,%2,%3}, {%4,%5,%6,%7}, {%8,%9}, {%0,%1,%2,%3};"
                        : "+f"(acc[mt][nt][0]), "+f"(acc[mt][nt][1]),
                          "+f"(acc[mt][nt][2]), "+f"(acc[mt][nt][3])
                        : "r"(af[mt][0]), "r"(af[mt][1]), "r"(af[mt][2]), "r"(af[mt][3]),
                          "r"(bf[nt][0]), "r"(bf[nt][1]));
                }
        }
        __syncthreads();
    }

#pragma unroll
    for (int mt = 0; mt < 2; mt++) {
        int r0 = m0 + wm + mt * 16 + g;
        int r1 = r0 + 8;
        int bi0 = (r0 < R) ? (r0 / rows_per_b) : 0;
        int bi1 = (r1 < R) ? (r1 / rows_per_b) : 0;
        float p0 = 0.f, p1 = 0.f;
#pragma unroll
        for (int nt = 0; nt < 8; nt++) {
            int n = n0 + wn + nt * 8 + tig * 2;
            float v0 = v[n], v1 = v[n + 1];
            p0 = fmaf(v0, tanhf(acc[mt][nt][0] + Cb[(size_t)bi0 * Hd + n]), p0);
            p0 = fmaf(v1, tanhf(acc[mt][nt][1] + Cb[(size_t)bi0 * Hd + n + 1]), p0);
            p1 = fmaf(v0, tanhf(acc[mt][nt][2] + Cb[(size_t)bi1 * Hd + n]), p1);
            p1 = fmaf(v1, tanhf(acc[mt][nt][3] + Cb[(size_t)bi1 * Hd + n + 1]), p1);
        }
        p0 += __shfl_xor_sync(0xffffffffu, p0, 1);
        p0 += __shfl_xor_sync(0xffffffffu, p0, 2);
        p1 += __shfl_xor_sync(0xffffffffu, p1, 1);
        p1 += __shfl_xor_sync(0xffffffffu, p1, 2);
        if (tig == 0) {
            if (r0 < R) atomicAdd(&out[r0], p0);
            if (r1 < R) atomicAdd(&out[r1], p1);
        }
    }
}

// ---------------- small kernels ----------------
__global__ void init_kernel(const float* __restrict__ bs,
                            const float* __restrict__ left_childs,
                            const float* __restrict__ cur_emb)
{
    int i = blockIdx.x * blockDim.x + threadIdx.x;
    if (i < Bd * Sd) { g_energy[i] = bs[0]; return; }
    i -= Bd * Sd;
    if (i < Bd * (NTOT + OPd)) { g_spre[i] = 0.f; return; }
    i -= Bd * (NTOT + OPd);
    if (i < Bd * 2 * Hd) {
        int r = i >> 11, c = i & (2 * Hd - 1);
        g_lc[i] = (c < Hd) ? left_childs[r * Hd + c] : cur_emb[r * Hd + c - Hd];
    }
}

__global__ void node_kernel(const unsigned char* __restrict__ lm, float* o_node) {
    __shared__ int smode;
    if (threadIdx.x == 0) {
        int mode = 0;
        bool nonalign = false;
        for (int t = 1; t < 64; t++)
            if ((t & 3) && lm[t]) { nonalign = true; break; }
        if (nonalign) {
            const unsigned int* w = (const unsigned int*)lm;
            bool isf = true;
            for (int t = 0; t < 16; t++) {
                unsigned int x = w[t];
                if (x != 0u && x != 0x3F800000u) { isf = false; break; }
            }
            mode = isf ? 2 : 1;
        }
        smode = mode;
    }
    __syncthreads();
    int i = blockIdx.x * blockDim.x + threadIdx.x;
    if (i >= Bd * Hd) return;
    int b = i >> 10;
    bool m;
    if (smode == 1)      m = lm[b] != 0;
    else if (smode == 2) m = ((const float*)lm)[b] != 0.f;
    else                 m = ((const int*)lm)[b] != 0;
    float lv = tanhf(g_pre[i]) * (1.f / (1.f + expf(-g_pre[Bd * Hd + i])));
    float rv = tanhf(g_pre[2 * Bd * Hd + i]) * (1.f / (1.f + expf(-g_pre[3 * Bd * Hd + i])));
    float nv = m ? rv : lv;
    g_node[i] = nv;
    o_node[i] = nv;
    g_cat[(size_t)b * 2 * Hd + (i & (Hd - 1))] = nv;
}

__global__ void softmax_kernel(const int* __restrict__ seq_mask) {
    int b = blockIdx.x, s = threadIdx.x;
    __shared__ float red[Sd];
    float val = g_energy[b * Sd + s];
    if (seq_mask[b * Sd + s] == 0) val = NEGV;
    red[s] = val; __syncthreads();
    for (int off = Sd / 2; off > 0; off >>= 1) {
        if (s < off) red[s] = fmaxf(red[s], red[s + off]);
        __syncthreads();
    }
    float mx = red[0]; __syncthreads();
    float ex = expf(val - mx);
    red[s] = ex; __syncthreads();
    for (int off = Sd / 2; off > 0; off >>= 1) {
        if (s < off) red[s] += red[s + off];
        __syncthreads();
    }
    g_energy[b * Sd + s] = ex / red[0];
}

__global__ void ctx_kernel(const float* __restrict__ enc, float* o_ctx) {
    int b = blockIdx.x;
    int h = blockIdx.y * 128 + threadIdx.x;
    __shared__ float aw[Sd];
    for (int i = threadIdx.x; i < Sd; i += 128) aw[i] = g_energy[b * Sd + i];
    __syncthreads();
    const float* ep = enc + (size_t)b * Sd * Hd + h;
    float s0 = 0.f;
#pragma unroll 4
    for (int t = 0; t < Sd; t++) s0 = fmaf(aw[t], ep[(size_t)t * Hd], s0);
    o_ctx[b * Hd + h] = s0;
    g_cat[(size_t)b * 2 * Hd + Hd + h] = s0;
}

__global__ void constnum_kernel(const float* __restrict__ cemb,
                                const float* __restrict__ pades, float* o_cn) {
    int i = blockIdx.x * blockDim.x + threadIdx.x;
    if (i >= Bd * NTOT * Hd) return;
    int h = i & (Hd - 1);
    int rn = i >> 10;
    int n = rn % NTOT, b = rn / NTOT;
    o_cn[i] = (n < NCd) ? cemb[n * Hd + h]
                        : pades[((size_t)b * NNd + (n - NCd)) * Hd + h];
}

__global__ void fin_kernel(const int* __restrict__ mask_nums, float* o_num, float* o_op) {
    int i = blockIdx.x * blockDim.x + threadIdx.x;
    if (i < Bd * NTOT) o_num[i] = mask_nums[i] ? g_spre[i] : NEGV;
    if (i < Bd * OPd)  o_op[i]  = g_spre[Bd * NTOT + i];
}

// ---------------- launch ----------------
extern "C" void kernel_launch(void* const* d_in, const int* in_sizes, int n_in,
                              void* d_out, int out_size)
{
    const float* cur_emb     = (const float*)d_in[0];
    const float* left_childs = (const float*)d_in[1];
    const unsigned char* left_mask = (const unsigned char*)d_in[2];
    const float* enc         = (const float*)d_in[3];
    const float* num_pades   = (const float*)d_in[4];
    const int*   seq_mask    = (const int*)d_in[5];
    const int*   mask_nums   = (const int*)d_in[6];
    const float* cemb        = (const float*)d_in[7];
    const float* opemb       = (const float*)d_in[8];
    const float* Wl   = (const float*)d_in[9];
    const float* bl   = (const float*)d_in[10];
    const float* Wlg  = (const float*)d_in[11];
    const float* blg  = (const float*)d_in[12];
    const float* Wr   = (const float*)d_in[13];
    const float* br   = (const float*)d_in[14];
    const float* Wrg  = (const float*)d_in[15];
    const float* brg  = (const float*)d_in[16];
    const float* Wleaf= (const float*)d_in[17];
    const float* bleaf= (const float*)d_in[18];
    const float* Wa   = (const float*)d_in[19];
    const float* ba   = (const float*)d_in[20];
    const float* Ws   = (const float*)d_in[21];
    const float* bs   = (const float*)d_in[22];
    const float* Wna  = (const float*)d_in[23];
    const float* bna  = (const float*)d_in[24];
    const float* Wns  = (const float*)d_in[25];
    const float* Woa  = (const float*)d_in[26];
    const float* boa  = (const float*)d_in[27];
    const float* Wos  = (const float*)d_in[28];

    float* out   = (float*)d_out;
    float* o_num = out;
    float* o_op  = out + 2240;
    float* o_node= out + 2560;
    float* o_ctx = out + 68096;
    float* o_cn  = out + 133632;
    float* o_ope = out + 2427392;

    void* p;
    cudaGetSymbolAddress(&p, g_pre);     float* pre_    = (float*)p;
    cudaGetSymbolAddress(&p, g_lc);      float* lc_     = (float*)p;
    cudaGetSymbolAddress(&p, g_node);    float* node_   = (float*)p;
    cudaGetSymbolAddress(&p, g_cnode);   float* cnode_  = (float*)p;
    cudaGetSymbolAddress(&p, g_energy);  float* energy_ = (float*)p;
    cudaGetSymbolAddress(&p, g_cat);     float* cat_    = (float*)p;
    cudaGetSymbolAddress(&p, g_leaf);    float* leaf_   = (float*)p;
    cudaGetSymbolAddress(&p, g_cnum);    float* cnum_   = (float*)p;
    cudaGetSymbolAddress(&p, g_cop);     float* cop_    = (float*)p;
    cudaGetSymbolAddress(&p, g_spre);    float* spre_   = (float*)p;

    const int BH = Bd * Hd;

    cudaFuncSetAttribute(mma_energy_gemm, cudaFuncAttributeMaxDynamicSharedMemorySize, ESMEM);

    // 1. init
    {
        int total = Bd * Sd + Bd * (NTOT + OPd) + 2 * BH;
        init_kernel<<<(total + 255) / 256, 256>>>(bs, left_childs, cur_emb);
    }
    cudaMemcpyAsync(o_ope, opemb, OPd * Hd * sizeof(float), cudaMemcpyDeviceToDevice, 0);

    // 2. node preacts
    {
        SkJobs js;
        js.j[0] = { cur_emb, Wl,  bl,  pre_,           Hd,     Hd,     Hd,     0 };
        js.j[1] = { cur_emb, Wlg, blg, pre_ + BH,      Hd,     Hd,     Hd,     0 };
        js.j[2] = { lc_,     Wr,  br,  pre_ + 2 * BH,  2 * Hd, 2 * Hd, 2 * Hd, 0 };
        js.j[3] = { lc_,     Wrg, brg, pre_ + 3 * BH,  2 * Hd, 2 * Hd, 2 * Hd, 0 };
        skinny_gemm<<<dim3(128, 4), 256>>>(js);
    }
    node_kernel<<<BH / 256, 256>>>(left_mask, o_node);

    // 3. cnode = ba + Wa[:, :H] @ node
    {
        SkJobs js;
        js.j[0] = { node_, Wa, ba, cnode_, Hd, 2 * Hd, Hd, 0 };
        skinny_gemm<<<dim3(128, 1), 256>>>(js);
    }

    // 4. const_num output (independent)
    constnum_kernel<<<(Bd * NTOT * Hd + 255) / 256, 256>>>(cemb, num_pades, o_cn);

    // 5. attention energies via cp.async mma.sync TF32 (launch #6 for ncu)
    mma_energy_gemm<<<dim3(4, 256), 256, ESMEM>>>(enc, Wa, cnode_, Ws, energy_);
    softmax_kernel<<<Bd, Sd>>>(seq_mask);
    dim3 gctx(Bd, 8);
    ctx_kernel<<<gctx, 128>>>(enc, o_ctx);

    // 6. leaf
    {
        SkJobs js;
        js.j[0] = { cat_, Wleaf, bleaf, leaf_, 2 * Hd, 2 * Hd, 2 * Hd, 1 };
        skinny_gemm<<<dim3(128, 1), 256>>>(js);
    }

    // 7. per-batch score biases
    {
        SkJobs js;
        js.j[0] = { leaf_, Wna, bna, cnum_, Hd, 3 * Hd, Hd, 0 };
        js.j[1] = { leaf_, Woa, boa, cop_,  Hd, 3 * Hd, Hd, 0 };
        skinny_gemm<<<dim3(128, 2), 256>>>(js);
    }

    // 8. score heads (mma.sync TF32 fused)
    {
        dim3 gnum(8, (Bd * NTOT + BM - 1) / BM);
        tf32_gemm_fused<<<gnum, 256>>>(o_cn, 0, 1, 0, leaf_,
                                       Wna, 3 * Hd, Hd, cnum_, Wns,
                                       spre_, Bd * NTOT, 2 * Hd, NTOT);
        dim3 gop(8, (Bd * OPd + BM - 1) / BM);
        tf32_gemm_fused<<<gop, 256>>>(opemb, 0, 2, OPd, leaf_,
                                      Woa, 3 * Hd, Hd, cop_, Wos,
                                      spre_ + Bd * NTOT, Bd * OPd, 2 * Hd, OPd);
    }

    fin_kernel<<<(Bd * NTOT + 255) / 256, 256>>>(mask_nums, o_num, o_op);
}

// round 6
// speedup vs baseline: 2.5534x; 1.1183x over previous
#include <cuda_runtime.h>
#include <cuda_bf16.h>
#include <cuda_fp16.h>
#include <cstdint>

#define Hd 1024
#define Bd 64
#define Sd 512
#define NCd 20
#define NNd 15
#define OPd 5
#define NTOT 35
#define NEGV (-1e12f)

// ---------------- scratch (device globals; no allocation allowed) ----------------
__device__ float g_pre[4 * Bd * Hd];
__device__ float g_lc[Bd * 2 * Hd];
__device__ float g_node[Bd * Hd];
__device__ float g_cnode[Bd * Hd];
__device__ float g_energy[Bd * Sd];
__device__ float g_cat[Bd * 2 * Hd];
__device__ float g_leaf[Bd * Hd];
__device__ float g_cnum[Bd * Hd];
__device__ float g_cop[Bd * Hd];
__device__ float g_spre[Bd * NTOT + Bd * OPd];
__device__ __half g_ench[32768 * 1024];   // enc in fp16 (64 MB)
__device__ __half g_wah[1024 * 1024];     // Wa[:, Hd:2Hd] in fp16 (2 MB)

// ================= helpers =================
__device__ __forceinline__ uint32_t smem_u32(const void* p) {
    uint32_t a;
    asm("{ .reg .u64 t; cvta.to.shared.u64 t, %1; cvt.u32.u64 %0, t; }" : "=r"(a) : "l"(p));
    return a;
}
__device__ __forceinline__ uint32_t f2tf32(float f) {
    uint32_t u;
    asm("cvt.rna.tf32.f32 %0, %1;" : "=r"(u) : "f"(f));
    return u;
}
__device__ __forceinline__ void cpasync16(uint32_t saddr, const void* g) {
    asm volatile("cp.async.cg.shared.global [%0], [%1], 16;" :: "r"(saddr), "l"(g));
}
#define CP_COMMIT() asm volatile("cp.async.commit_group;" ::: "memory")
#define CP_WAIT2()  asm volatile("cp.async.wait_group 2;" ::: "memory")
#define CP_WAIT1()  asm volatile("cp.async.wait_group 1;" ::: "memory")
#define CP_WAIT0()  asm volatile("cp.async.wait_group 0;" ::: "memory")

// ---------------- fp32 -> fp16 convert pre-pass ----------------
__global__ void cvt_kernel(const float* __restrict__ enc, const float* __restrict__ Wa) {
    const int EN4 = (32768 * 1024) / 4;
    int i = blockIdx.x * blockDim.x + threadIdx.x;
    if (i < EN4) {
        float4 a = ((const float4*)enc)[i];
        __half2 h0 = __floats2half2_rn(a.x, a.y);
        __half2 h1 = __floats2half2_rn(a.z, a.w);
        uint2 u;
        u.x = *(uint32_t*)&h0; u.y = *(uint32_t*)&h1;
        *(uint2*)(g_ench + (size_t)i * 4) = u;
    } else {
        int j = i - EN4;
        if (j < (1024 * 1024) / 4) {
            int n = j >> 8, c = j & 255;
            float4 a = *(const float4*)(Wa + (size_t)n * 2048 + 1024 + c * 4);
            __half2 h0 = __floats2half2_rn(a.x, a.y);
            __half2 h1 = __floats2half2_rn(a.z, a.w);
            uint2 u;
            u.x = *(uint32_t*)&h0; u.y = *(uint32_t*)&h1;
            *(uint2*)(g_wah + (size_t)n * 1024 + c * 4) = u;
        }
    }
}

// =================================================================================
// FP16 m16n8k16 energies GEMM, 4-stage cp.async, fused tanh*Ws epilogue
//   D[32768 x 1024] = ench @ wah^T;  out[row] += sum_n Ws[n]*tanh(D+Cb[row/Sd])
//   CTA 128x256, warp 64x64 (8 warps 2x4), BK=32 halves.
// =================================================================================
#define FP2 20                       // smem pitch in b32 units (16 data + 4 pad)
#define FSTG ((128 + 256) * FP2)     // b32 per stage = 7680
#define FSMEM (4 * FSTG * 4)         // 122880 bytes

__global__ __launch_bounds__(256) void mma_energy_f16(
    const __half* __restrict__ Ah, const __half* __restrict__ Bh,
    const float* __restrict__ Cb, const float* __restrict__ v,
    float* __restrict__ outp)
{
    extern __shared__ __align__(16) uint32_t fsm[];
    const int tid = threadIdx.x;
    const int n0 = blockIdx.x * 256;
    const int m0 = blockIdx.y * 128;
    const int warp = tid >> 5, lane = tid & 31;
    const int g = lane >> 2, tig = lane & 3;
    const int wm = (warp >> 2) * 64;
    const int wn = (warp & 3) * 64;
    const uint32_t sbase = smem_u32(fsm);

    float acc[4][8][4];
#pragma unroll
    for (int mt = 0; mt < 4; mt++)
#pragma unroll
        for (int nt = 0; nt < 8; nt++)
#pragma unroll
            for (int c = 0; c < 4; c++) acc[mt][nt][c] = 0.f;

#define FPF(c_) do {                                                              \
    const uint32_t _sb = sbase + ((uint32_t)((c_) & 3)) * (FSTG * 4);             \
    const int _k0 = (c_) * 32;                                                    \
    _Pragma("unroll")                                                             \
    for (int it = 0; it < 2; it++) {                                              \
        int idx = tid + it * 256; int r = idx >> 2, pp = idx & 3;                 \
        cpasync16(_sb + (uint32_t)(r * FP2 + pp * 4) * 4,                         \
                  Ah + (size_t)(m0 + r) * 1024 + _k0 + pp * 8);                   \
    }                                                                             \
    _Pragma("unroll")                                                             \
    for (int it = 0; it < 4; it++) {                                              \
        int idx = tid + it * 256; int r = idx >> 2, pp = idx & 3;                 \
        cpasync16(_sb + (uint32_t)(2560 + r * FP2 + pp * 4) * 4,                  \
                  Bh + (size_t)(n0 + r) * 1024 + _k0 + pp * 8);                   \
    }                                                                             \
    CP_COMMIT();                                                                  \
} while (0)

    FPF(0); FPF(1); FPF(2);

    for (int c = 0; c < 32; c++) {
        const int rem = 31 - c;
        if (rem >= 2) CP_WAIT2(); else if (rem == 1) CP_WAIT1(); else CP_WAIT0();
        __syncthreads();
        if (c + 3 < 32) FPF(c + 3);

        const uint32_t* Au = fsm + (c & 3) * FSTG;
        const uint32_t* Bu = Au + 2560;

#pragma unroll
        for (int kk = 0; kk < 2; kk++) {           // two k16 steps
            uint32_t af[4][4];
#pragma unroll
            for (int mt = 0; mt < 4; mt++) {
                const int b0 = (wm + mt * 16 + g) * FP2 + kk * 8 + tig;
                const int b1 = b0 + 8 * FP2;
                af[mt][0] = Au[b0];
                af[mt][1] = Au[b1];
                af[mt][2] = Au[b0 + 4];
                af[mt][3] = Au[b1 + 4];
            }
            uint32_t bf[8][2];
#pragma unroll
            for (int nt = 0; nt < 8; nt++) {
                const int bb = (wn + nt * 8 + g) * FP2 + kk * 8 + tig;
                bf[nt][0] = Bu[bb];
                bf[nt][1] = Bu[bb + 4];
            }
#pragma unroll
            for (int mt = 0; mt < 4; mt++)
#pragma unroll
                for (int nt = 0; nt < 8; nt++) {
                    asm volatile(
                        "mma.sync.aligned.m16n8k16.row.col.f32.f16.f16.f32 "
                        "{%0,%1,%2,%3}, {%4,%5,%6,%7}, {%8,%9}, {%0,%1,%2,%3};"
                        : "+f"(acc[mt][nt][0]), "+f"(acc[mt][nt][1]),
                          "+f"(acc[mt][nt][2]), "+f"(acc[mt][nt][3])
                        : "r"(af[mt][0]), "r"(af[mt][1]), "r"(af[mt][2]), "r"(af[mt][3]),
                          "r"(bf[nt][0]), "r"(bf[nt][1]));
                }
        }
    }

    // fused epilogue: per-row Ws-weighted tanh reduction (all rows valid)
#pragma unroll
    for (int mt = 0; mt < 4; mt++) {
        const int r0 = m0 + wm + mt * 16 + g;
        const int r1 = r0 + 8;
        const int bi0 = r0 >> 9;
        const int bi1 = r1 >> 9;
        float p0 = 0.f, p1 = 0.f;
#pragma unroll
        for (int nt = 0; nt < 8; nt++) {
            const int n = n0 + wn + nt * 8 + tig * 2;
            const float v0 = v[n], v1 = v[n + 1];
            p0 = fmaf(v0, tanhf(acc[mt][nt][0] + Cb[(size_t)bi0 * Hd + n]), p0);
            p0 = fmaf(v1, tanhf(acc[mt][nt][1] + Cb[(size_t)bi0 * Hd + n + 1]), p0);
            p1 = fmaf(v0, tanhf(acc[mt][nt][2] + Cb[(size_t)bi1 * Hd + n]), p1);
            p1 = fmaf(v1, tanhf(acc[mt][nt][3] + Cb[(size_t)bi1 * Hd + n + 1]), p1);
        }
        p0 += __shfl_xor_sync(0xffffffffu, p0, 1);
        p0 += __shfl_xor_sync(0xffffffffu, p0, 2);
        p1 += __shfl_xor_sync(0xffffffffu, p1, 1);
        p1 += __shfl_xor_sync(0xffffffffu, p1, 2);
        if (tig == 0) {
            atomicAdd(&outp[r0], p0);
            atomicAdd(&outp[r1], p1);
        }
    }
}

// =================================================================================
// Skinny GEMM: one warp per output column (unchanged)
// =================================================================================
struct SkJob {
    const float* A;
    const float* W;
    const float* bias;
    float* out;
    int lda, ldw, K, act;
};
struct SkJobs { SkJob j[4]; };

#define SK_CHUNK 128

__global__ __launch_bounds__(256) void skinny_gemm(SkJobs jobs) {
    const SkJob jb = jobs.j[blockIdx.y];
    __shared__ __align__(16) float As[64][SK_CHUNK];
    const int tid = threadIdx.x, warp = tid >> 5, lane = tid & 31;
    const int n = blockIdx.x * 8 + warp;
    const float* wrow = jb.W + (size_t)n * jb.ldw;

    float acc[64];
#pragma unroll
    for (int r = 0; r < 64; r++) acc[r] = 0.f;

    for (int kc = 0; kc < jb.K; kc += SK_CHUNK) {
        __syncthreads();
#pragma unroll
        for (int it = 0; it < 8; it++) {
            int idx = tid + it * 256;
            int r = idx >> 5, c = idx & 31;
            *(float4*)&As[r][c * 4] =
                *(const float4*)(jb.A + (size_t)r * jb.lda + kc + c * 4);
        }
        __syncthreads();
        float4 w = *(const float4*)(wrow + kc + lane * 4);
#pragma unroll
        for (int r = 0; r < 64; r++) {
            float4 a = *(const float4*)&As[r][lane * 4];
            acc[r] = fmaf(w.x, a.x, acc[r]);
            acc[r] = fmaf(w.y, a.y, acc[r]);
            acc[r] = fmaf(w.z, a.z, acc[r]);
            acc[r] = fmaf(w.w, a.w, acc[r]);
        }
    }
#pragma unroll
    for (int off = 16; off; off >>= 1)
#pragma unroll
        for (int r = 0; r < 64; r++)
            acc[r] += __shfl_xor_sync(0xffffffffu, acc[r], off);

    float bv = jb.bias[n];
    float v0 = acc[lane] + bv;
    float v1 = acc[32 + lane] + bv;
    if (jb.act == 1) { v0 = tanhf(v0); v1 = tanhf(v1); }
    jb.out[(size_t)lane * Hd + n] = v0;
    jb.out[(size_t)(32 + lane) * Hd + n] = v1;
}

// =================================================================================
// mma.sync TF32 fused GEMM (score heads)
// =================================================================================
#define BM 128
#define BN 128
#define BKt 32
#define PITCH 36

__global__ __launch_bounds__(256) void tf32_gemm_fused(
    const float* __restrict__ A, int lda, int amode, int rowmod,
    const float* __restrict__ leaf,
    const float* __restrict__ W, int ldw, int woff,
    const float* __restrict__ Cb, const float* __restrict__ v,
    float* __restrict__ out, int R, int K, int rows_per_b)
{
    __shared__ __align__(16) uint32_t As[BM * PITCH];
    __shared__ __align__(16) uint32_t Bs[BN * PITCH];

    const int tid = threadIdx.x;
    const int n0 = blockIdx.x * BN;
    const int m0 = blockIdx.y * BM;
    const int warp = tid >> 5, lane = tid & 31;
    const int g = lane >> 2, tig = lane & 3;
    const int wm = (warp >> 1) * 32;
    const int wn = (warp & 1) * 64;

    float acc[2][8][4];
#pragma unroll
    for (int mt = 0; mt < 2; mt++)
#pragma unroll
        for (int nt = 0; nt < 8; nt++)
#pragma unroll
            for (int c = 0; c < 4; c++) acc[mt][nt][c] = 0.f;

    for (int k0 = 0; k0 < K; k0 += BKt) {
#pragma unroll
        for (int it = 0; it < 4; it++) {
            int idx = tid + it * 256;
            int r = idx >> 3, c4 = idx & 7;
            int gr = m0 + r, gc = k0 + c4 * 4;
            float4 av = make_float4(0.f, 0.f, 0.f, 0.f);
            if (gr < R) {
                if (amode == 0) {
                    av = *(const float4*)(A + (size_t)gr * lda + gc);
                } else {
                    int xr = (amode == 2) ? (gr % rowmod) : gr;
                    if (gc < Hd) {
                        av = *(const float4*)(A + (size_t)xr * Hd + gc);
                    } else {
                        int h = gc - Hd;
                        int b = gr / rows_per_b;
                        av = *(const float4*)(A + (size_t)xr * Hd + h);
                        float4 lf = *(const float4*)(leaf + (size_t)b * Hd + h);
                        av.x *= lf.x; av.y *= lf.y; av.z *= lf.z; av.w *= lf.w;
                    }
                }
            }
            float4 bv = *(const float4*)(W + (size_t)(n0 + r) * ldw + woff + gc);
            uint4 ua, ub;
            ua.x = f2tf32(av.x); ua.y = f2tf32(av.y);
            ua.z = f2tf32(av.z); ua.w = f2tf32(av.w);
            ub.x = f2tf32(bv.x); ub.y = f2tf32(bv.y);
            ub.z = f2tf32(bv.z); ub.w = f2tf32(bv.w);
            *(uint4*)&As[r * PITCH + c4 * 4] = ua;
            *(uint4*)&Bs[r * PITCH + c4 * 4] = ub;
        }
        __syncthreads();

#pragma unroll
        for (int kk = 0; kk < BKt; kk += 8) {
            uint32_t af[2][4];
#pragma unroll
            for (int mt = 0; mt < 2; mt++) {
                int base = (wm + mt * 16 + g) * PITCH + kk;
                af[mt][0] = As[base + tig];
                af[mt][1] = As[base + 8 * PITCH + tig];
                af[mt][2] = As[base + tig + 4];
                af[mt][3] = As[base + 8 * PITCH + tig + 4];
            }
            uint32_t bf[8][2];
#pragma unroll
            for (int nt = 0; nt < 8; nt++) {
                int base = (wn + nt * 8 + g) * PITCH + kk;
                bf[nt][0] = Bs[base + tig];
                bf[nt][1] = Bs[base + tig + 4];
            }
#pragma unroll
            for (int mt = 0; mt < 2; mt++)
#pragma unroll
                for (int nt = 0; nt < 8; nt++) {
                    asm volatile(
                        "mma.sync.aligned.m16n8k8.row.col.f32.tf32.tf32.f32 "
                        "{%0,%1,%2,%3}, {%4,%5,%6,%7}, {%8,%9}, {%0,%1,%2,%3};"
                        : "+f"(acc[mt][nt][0]), "+f"(acc[mt][nt][1]),
                          "+f"(acc[mt][nt][2]), "+f"(acc[mt][nt][3])
                        : "r"(af[mt][0]), "r"(af[mt][1]), "r"(af[mt][2]), "r"(af[mt][3]),
                          "r"(bf[nt][0]), "r"(bf[nt][1]));
                }
        }
        __syncthreads();
    }

#pragma unroll
    for (int mt = 0; mt < 2; mt++) {
        int r0 = m0 + wm + mt * 16 + g;
        int r1 = r0 + 8;
        int bi0 = (r0 < R) ? (r0 / rows_per_b) : 0;
        int bi1 = (r1 < R) ? (r1 / rows_per_b) : 0;
        float p0 = 0.f, p1 = 0.f;
#pragma unroll
        for (int nt = 0; nt < 8; nt++) {
            int n = n0 + wn + nt * 8 + tig * 2;
            float v0 = v[n], v1 = v[n + 1];
            p0 = fmaf(v0, tanhf(acc[mt][nt][0] + Cb[(size_t)bi0 * Hd + n]), p0);
            p0 = fmaf(v1, tanhf(acc[mt][nt][1] + Cb[(size_t)bi0 * Hd + n + 1]), p0);
            p1 = fmaf(v0, tanhf(acc[mt][nt][2] + Cb[(size_t)bi1 * Hd + n]), p1);
            p1 = fmaf(v1, tanhf(acc[mt][nt][3] + Cb[(size_t)bi1 * Hd + n + 1]), p1);
        }
        p0 += __shfl_xor_sync(0xffffffffu, p0, 1);
        p0 += __shfl_xor_sync(0xffffffffu, p0, 2);
        p1 += __shfl_xor_sync(0xffffffffu, p1, 1);
        p1 += __shfl_xor_sync(0xffffffffu, p1, 2);
        if (tig == 0) {
            if (r0 < R) atomicAdd(&out[r0], p0);
            if (r1 < R) atomicAdd(&out[r1], p1);
        }
    }
}

// ---------------- small kernels ----------------
__global__ void init_kernel(const float* __restrict__ bs,
                            const float* __restrict__ left_childs,
                            const float* __restrict__ cur_emb)
{
    int i = blockIdx.x * blockDim.x + threadIdx.x;
    if (i < Bd * Sd) { g_energy[i] = bs[0]; return; }
    i -= Bd * Sd;
    if (i < Bd * (NTOT + OPd)) { g_spre[i] = 0.f; return; }
    i -= Bd * (NTOT + OPd);
    if (i < Bd * 2 * Hd) {
        int r = i >> 11, c = i & (2 * Hd - 1);
        g_lc[i] = (c < Hd) ? left_childs[r * Hd + c] : cur_emb[r * Hd + c - Hd];
    }
}

__global__ void node_kernel(const unsigned char* __restrict__ lm, float* o_node) {
    __shared__ int smode;
    if (threadIdx.x == 0) {
        int mode = 0;
        bool nonalign = false;
        for (int t = 1; t < 64; t++)
            if ((t & 3) && lm[t]) { nonalign = true; break; }
        if (nonalign) {
            const unsigned int* w = (const unsigned int*)lm;
            bool isf = true;
            for (int t = 0; t < 16; t++) {
                unsigned int x = w[t];
                if (x != 0u && x != 0x3F800000u) { isf = false; break; }
            }
            mode = isf ? 2 : 1;
        }
        smode = mode;
    }
    __syncthreads();
    int i = blockIdx.x * blockDim.x + threadIdx.x;
    if (i >= Bd * Hd) return;
    int b = i >> 10;
    bool m;
    if (smode == 1)      m = lm[b] != 0;
    else if (smode == 2) m = ((const float*)lm)[b] != 0.f;
    else                 m = ((const int*)lm)[b] != 0;
    float lv = tanhf(g_pre[i]) * (1.f / (1.f + expf(-g_pre[Bd * Hd + i])));
    float rv = tanhf(g_pre[2 * Bd * Hd + i]) * (1.f / (1.f + expf(-g_pre[3 * Bd * Hd + i])));
    float nv = m ? rv : lv;
    g_node[i] = nv;
    o_node[i] = nv;
    g_cat[(size_t)b * 2 * Hd + (i & (Hd - 1))] = nv;
}

__global__ void softmax_kernel(const int* __restrict__ seq_mask) {
    int b = blockIdx.x, s = threadIdx.x;
    __shared__ float red[Sd];
    float val = g_energy[b * Sd + s];
    if (seq_mask[b * Sd + s] == 0) val = NEGV;
    red[s] = val; __syncthreads();
    for (int off = Sd / 2; off > 0; off >>= 1) {
        if (s < off) red[s] = fmaxf(red[s], red[s + off]);
        __syncthreads();
    }
    float mx = red[0]; __syncthreads();
    float ex = expf(val - mx);
    red[s] = ex; __syncthreads();
    for (int off = Sd / 2; off > 0; off >>= 1) {
        if (s < off) red[s] += red[s + off];
        __syncthreads();
    }
    g_energy[b * Sd + s] = ex / red[0];
}

__global__ void ctx_kernel(const float* __restrict__ enc, float* o_ctx) {
    int b = blockIdx.x;
    int h = blockIdx.y * 128 + threadIdx.x;
    __shared__ float aw[Sd];
    for (int i = threadIdx.x; i < Sd; i += 128) aw[i] = g_energy[b * Sd + i];
    __syncthreads();
    const float* ep = enc + (size_t)b * Sd * Hd + h;
    float s0 = 0.f;
#pragma unroll 4
    for (int t = 0; t < Sd; t++) s0 = fmaf(aw[t], ep[(size_t)t * Hd], s0);
    o_ctx[b * Hd + h] = s0;
    g_cat[(size_t)b * 2 * Hd + Hd + h] = s0;
}

__global__ void constnum_kernel(const float* __restrict__ cemb,
                                const float* __restrict__ pades, float* o_cn) {
    int i = blockIdx.x * blockDim.x + threadIdx.x;
    if (i >= Bd * NTOT * Hd) return;
    int h = i & (Hd - 1);
    int rn = i >> 10;
    int n = rn % NTOT, b = rn / NTOT;
    o_cn[i] = (n < NCd) ? cemb[n * Hd + h]
                        : pades[((size_t)b * NNd + (n - NCd)) * Hd + h];
}

__global__ void fin_kernel(const int* __restrict__ mask_nums, float* o_num, float* o_op) {
    int i = blockIdx.x * blockDim.x + threadIdx.x;
    if (i < Bd * NTOT) o_num[i] = mask_nums[i] ? g_spre[i] : NEGV;
    if (i < Bd * OPd)  o_op[i]  = g_spre[Bd * NTOT + i];
}

// ---------------- launch ----------------
extern "C" void kernel_launch(void* const* d_in, const int* in_sizes, int n_in,
                              void* d_out, int out_size)
{
    const float* cur_emb     = (const float*)d_in[0];
    const float* left_childs = (const float*)d_in[1];
    const unsigned char* left_mask = (const unsigned char*)d_in[2];
    const float* enc         = (const float*)d_in[3];
    const float* num_pades   = (const float*)d_in[4];
    const int*   seq_mask    = (const int*)d_in[5];
    const int*   mask_nums   = (const int*)d_in[6];
    const float* cemb        = (const float*)d_in[7];
    const float* opemb       = (const float*)d_in[8];
    const float* Wl   = (const float*)d_in[9];
    const float* bl   = (const float*)d_in[10];
    const float* Wlg  = (const float*)d_in[11];
    const float* blg  = (const float*)d_in[12];
    const float* Wr   = (const float*)d_in[13];
    const float* br   = (const float*)d_in[14];
    const float* Wrg  = (const float*)d_in[15];
    const float* brg  = (const float*)d_in[16];
    const float* Wleaf= (const float*)d_in[17];
    const float* bleaf= (const float*)d_in[18];
    const float* Wa   = (const float*)d_in[19];
    const float* ba   = (const float*)d_in[20];
    const float* Ws   = (const float*)d_in[21];
    const float* bs   = (const float*)d_in[22];
    const float* Wna  = (const float*)d_in[23];
    const float* bna  = (const float*)d_in[24];
    const float* Wns  = (const float*)d_in[25];
    const float* Woa  = (const float*)d_in[26];
    const float* boa  = (const float*)d_in[27];
    const float* Wos  = (const float*)d_in[28];

    float* out   = (float*)d_out;
    float* o_num = out;
    float* o_op  = out + 2240;
    float* o_node= out + 2560;
    float* o_ctx = out + 68096;
    float* o_cn  = out + 133632;
    float* o_ope = out + 2427392;

    void* p;
    cudaGetSymbolAddress(&p, g_pre);     float* pre_    = (float*)p;
    cudaGetSymbolAddress(&p, g_lc);      float* lc_     = (float*)p;
    cudaGetSymbolAddress(&p, g_node);    float* node_   = (float*)p;
    cudaGetSymbolAddress(&p, g_cnode);   float* cnode_  = (float*)p;
    cudaGetSymbolAddress(&p, g_energy);  float* energy_ = (float*)p;
    cudaGetSymbolAddress(&p, g_cat);     float* cat_    = (float*)p;
    cudaGetSymbolAddress(&p, g_leaf);    float* leaf_   = (float*)p;
    cudaGetSymbolAddress(&p, g_cnum);    float* cnum_   = (float*)p;
    cudaGetSymbolAddress(&p, g_cop);     float* cop_    = (float*)p;
    cudaGetSymbolAddress(&p, g_spre);    float* spre_   = (float*)p;
    cudaGetSymbolAddress(&p, g_ench);    __half* ench_  = (__half*)p;
    cudaGetSymbolAddress(&p, g_wah);     __half* wah_   = (__half*)p;

    const int BH = Bd * Hd;

    cudaFuncSetAttribute(mma_energy_f16, cudaFuncAttributeMaxDynamicSharedMemorySize, FSMEM);

    // 1. fp16 convert pre-pass (independent, feeds energies GEMM)
    {
        int tot4 = (32768 * 1024 + 1024 * 1024) / 4;
        cvt_kernel<<<(tot4 + 255) / 256, 256>>>(enc, Wa);
    }

    // 2. init (energy seed / spre zero / lc concat)
    {
        int total = Bd * Sd + Bd * (NTOT + OPd) + 2 * BH;
        init_kernel<<<(total + 255) / 256, 256>>>(bs, left_childs, cur_emb);
    }

    // 3. node preacts
    {
        SkJobs js;
        js.j[0] = { cur_emb, Wl,  bl,  pre_,           Hd,     Hd,     Hd,     0 };
        js.j[1] = { cur_emb, Wlg, blg, pre_ + BH,      Hd,     Hd,     Hd,     0 };
        js.j[2] = { lc_,     Wr,  br,  pre_ + 2 * BH,  2 * Hd, 2 * Hd, 2 * Hd, 0 };
        js.j[3] = { lc_,     Wrg, brg, pre_ + 3 * BH,  2 * Hd, 2 * Hd, 2 * Hd, 0 };
        skinny_gemm<<<dim3(128, 4), 256>>>(js);
    }
    node_kernel<<<BH / 256, 256>>>(left_mask, o_node);

    // 4. cnode = ba + Wa[:, :H] @ node
    {
        SkJobs js;
        js.j[0] = { node_, Wa, ba, cnode_, Hd, 2 * Hd, Hd, 0 };
        skinny_gemm<<<dim3(128, 1), 256>>>(js);
    }

    // 5. attention energies via fp16 mma (launch #6 for ncu)
    mma_energy_f16<<<dim3(4, 256), 256, FSMEM>>>(ench_, wah_, cnode_, Ws, energy_);
    softmax_kernel<<<Bd, Sd>>>(seq_mask);
    dim3 gctx(Bd, 8);
    ctx_kernel<<<gctx, 128>>>(enc, o_ctx);

    // 6. const_num output (independent)
    constnum_kernel<<<(Bd * NTOT * Hd + 255) / 256, 256>>>(cemb, num_pades, o_cn);

    // 7. leaf
    {
        SkJobs js;
        js.j[0] = { cat_, Wleaf, bleaf, leaf_, 2 * Hd, 2 * Hd, 2 * Hd, 1 };
        skinny_gemm<<<dim3(128, 1), 256>>>(js);
    }

    // 8. per-batch score biases
    {
        SkJobs js;
        js.j[0] = { leaf_, Wna, bna, cnum_, Hd, 3 * Hd, Hd, 0 };
        js.j[1] = { leaf_, Woa, boa, cop_,  Hd, 3 * Hd, Hd, 0 };
        skinny_gemm<<<dim3(128, 2), 256>>>(js);
    }

    // 9. score heads (mma.sync TF32 fused)
    {
        dim3 gnum(8, (Bd * NTOT + BM - 1) / BM);
        tf32_gemm_fused<<<gnum, 256>>>(o_cn, 0, 1, 0, leaf_,
                                       Wna, 3 * Hd, Hd, cnum_, Wns,
                                       spre_, Bd * NTOT, 2 * Hd, NTOT);
        dim3 gop(8, (Bd * OPd + BM - 1) / BM);
        tf32_gemm_fused<<<gop, 256>>>(opemb, 0, 2, OPd, leaf_,
                                      Woa, 3 * Hd, Hd, cop_, Wos,
                                      spre_ + Bd * NTOT, Bd * OPd, 2 * Hd, OPd);
    }

    fin_kernel<<<(Bd * NTOT + 255) / 256, 256>>>(mask_nums, o_num, o_op);
    cudaMemcpyAsync(o_ope, opemb, OPd * Hd * sizeof(float), cudaMemcpyDeviceToDevice, 0);
}

// round 7
// speedup vs baseline: 3.0168x; 1.1815x over previous
#include <cuda_runtime.h>
#include <cuda_bf16.h>
#include <cuda_fp16.h>
#include <cstdint>

#define Hd 1024
#define Bd 64
#define Sd 512
#define NCd 20
#define NNd 15
#define OPd 5
#define NTOT 35
#define NEGV (-1e12f)

// ---------------- scratch (device globals; no allocation allowed) ----------------
__device__ float g_pre[4 * Bd * Hd];
__device__ float g_lc[Bd * 2 * Hd];
__device__ float g_node[Bd * Hd];
__device__ float g_cnode[Bd * Hd];
__device__ float g_energy[Bd * Sd];
__device__ float g_cat[Bd * 2 * Hd];
__device__ float g_leaf[Bd * Hd];
__device__ float g_cnum[Bd * Hd];
__device__ float g_cop[Bd * Hd];
__device__ float g_spre[Bd * NTOT + Bd * OPd];
__device__ __half g_ench[32768 * 1024];   // enc in fp16 (64 MB)
__device__ __half g_wah[1024 * 1024];     // Wa[:, Hd:2Hd] in fp16 (2 MB)

// ================= helpers =================
__device__ __forceinline__ uint32_t smem_u32(const void* p) {
    uint32_t a;
    asm("{ .reg .u64 t; cvta.to.shared.u64 t, %1; cvt.u32.u64 %0, t; }" : "=r"(a) : "l"(p));
    return a;
}
__device__ __forceinline__ uint32_t f2tf32(float f) {
    uint32_t u;
    asm("cvt.rna.tf32.f32 %0, %1;" : "=r"(u) : "f"(f));
    return u;
}
__device__ __forceinline__ void cpasync16(uint32_t saddr, const void* g) {
    asm volatile("cp.async.cg.shared.global [%0], [%1], 16;" :: "r"(saddr), "l"(g));
}
#define CP_COMMIT() asm volatile("cp.async.commit_group;" ::: "memory")
#define CP_WAIT2()  asm volatile("cp.async.wait_group 2;" ::: "memory")
#define CP_WAIT1()  asm volatile("cp.async.wait_group 1;" ::: "memory")
#define CP_WAIT0()  asm volatile("cp.async.wait_group 0;" ::: "memory")

// ---------------- fp32 -> fp16 convert pre-pass ----------------
__global__ void cvt_kernel(const float* __restrict__ enc, const float* __restrict__ Wa) {
    const int EN4 = (32768 * 1024) / 4;
    int i = blockIdx.x * blockDim.x + threadIdx.x;
    if (i < EN4) {
        float4 a = ((const float4*)enc)[i];
        __half2 h0 = __floats2half2_rn(a.x, a.y);
        __half2 h1 = __floats2half2_rn(a.z, a.w);
        uint2 u;
        u.x = *(uint32_t*)&h0; u.y = *(uint32_t*)&h1;
        *(uint2*)(g_ench + (size_t)i * 4) = u;
    } else {
        int j = i - EN4;
        if (j < (1024 * 1024) / 4) {
            int n = j >> 8, c = j & 255;
            float4 a = *(const float4*)(Wa + (size_t)n * 2048 + 1024 + c * 4);
            __half2 h0 = __floats2half2_rn(a.x, a.y);
            __half2 h1 = __floats2half2_rn(a.z, a.w);
            uint2 u;
            u.x = *(uint32_t*)&h0; u.y = *(uint32_t*)&h1;
            *(uint2*)(g_wah + (size_t)n * 1024 + c * 4) = u;
        }
    }
}

// =================================================================================
// FP16 m16n8k16 energies GEMM, 3-stage cp.async, 2 CTAs/SM
//   D[32768 x 1024] = ench @ wah^T;  out[row] += sum_n Ws[n]*tanh(D+Cb[row/Sd])
//   CTA 128x128 (128 threads, 4 warps of 64x64), BK=32 halves.
// =================================================================================
#define FP2 20                        // smem pitch in b32 (16 data + 4 pad)
#define FSTG ((128 + 128) * FP2)      // b32 per stage = 5120
#define FSMEM (3 * FSTG * 4)          // 61440 bytes

__global__ __launch_bounds__(128) void mma_energy_f16(
    const __half* __restrict__ Ah, const __half* __restrict__ Bh,
    const float* __restrict__ Cb, const float* __restrict__ v,
    float* __restrict__ outp)
{
    extern __shared__ __align__(16) uint32_t fsm[];
    const int tid = threadIdx.x;
    const int n0 = blockIdx.x * 128;     // x fast -> CTAs with same m share A via L2
    const int m0 = blockIdx.y * 128;
    const int warp = tid >> 5, lane = tid & 31;
    const int g = lane >> 2, tig = lane & 3;
    const int wm = (warp & 1) * 64;
    const int wn = (warp >> 1) * 64;
    const uint32_t sbase = smem_u32(fsm);

    float acc[4][8][4];
#pragma unroll
    for (int mt = 0; mt < 4; mt++)
#pragma unroll
        for (int nt = 0; nt < 8; nt++)
#pragma unroll
            for (int c = 0; c < 4; c++) acc[mt][nt][c] = 0.f;

#define FPF(c_) do {                                                              \
    const uint32_t _sb = sbase + (uint32_t)((c_) % 3) * (FSTG * 4);               \
    const int _k0 = (c_) * 32;                                                    \
    _Pragma("unroll")                                                             \
    for (int it = 0; it < 4; it++) {                                              \
        int idx = tid + it * 128; int r = idx >> 2, pp = idx & 3;                 \
        cpasync16(_sb + (uint32_t)(r * FP2 + pp * 4) * 4,                         \
                  Ah + (size_t)(m0 + r) * 1024 + _k0 + pp * 8);                   \
    }                                                                             \
    _Pragma("unroll")                                                             \
    for (int it = 0; it < 4; it++) {                                              \
        int idx = tid + it * 128; int r = idx >> 2, pp = idx & 3;                 \
        cpasync16(_sb + (uint32_t)((2560 + r * FP2 + pp * 4)) * 4,                \
                  Bh + (size_t)(n0 + r) * 1024 + _k0 + pp * 8);                   \
    }                                                                             \
    CP_COMMIT();                                                                  \
} while (0)

    FPF(0); FPF(1); FPF(2);

    for (int c = 0; c < 32; c++) {
        if (c < 30) CP_WAIT2(); else if (c == 30) CP_WAIT1(); else CP_WAIT0();
        __syncthreads();

        const uint32_t* Au = fsm + (c % 3) * FSTG;
        const uint32_t* Bu = Au + 2560;

#pragma unroll
        for (int kk = 0; kk < 2; kk++) {
            uint32_t af[4][4];
#pragma unroll
            for (int mt = 0; mt < 4; mt++) {
                const int b0 = (wm + mt * 16 + g) * FP2 + kk * 8 + tig;
                const int b1 = b0 + 8 * FP2;
                af[mt][0] = Au[b0];
                af[mt][1] = Au[b1];
                af[mt][2] = Au[b0 + 4];
                af[mt][3] = Au[b1 + 4];
            }
            uint32_t bf[8][2];
#pragma unroll
            for (int nt = 0; nt < 8; nt++) {
                const int bb = (wn + nt * 8 + g) * FP2 + kk * 8 + tig;
                bf[nt][0] = Bu[bb];
                bf[nt][1] = Bu[bb + 4];
            }
#pragma unroll
            for (int mt = 0; mt < 4; mt++)
#pragma unroll
                for (int nt = 0; nt < 8; nt++) {
                    asm volatile(
                        "mma.sync.aligned.m16n8k16.row.col.f32.f16.f16.f32 "
                        "{%0,%1,%2,%3}, {%4,%5,%6,%7}, {%8,%9}, {%0,%1,%2,%3};"
                        : "+f"(acc[mt][nt][0]), "+f"(acc[mt][nt][1]),
                          "+f"(acc[mt][nt][2]), "+f"(acc[mt][nt][3])
                        : "r"(af[mt][0]), "r"(af[mt][1]), "r"(af[mt][2]), "r"(af[mt][3]),
                          "r"(bf[nt][0]), "r"(bf[nt][1]));
                }
        }
        __syncthreads();              // all warps done with stage c before overwrite
        if (c + 3 < 32) FPF(c + 3);
    }

    // fused epilogue: per-row Ws-weighted tanh reduction (all rows valid)
#pragma unroll
    for (int mt = 0; mt < 4; mt++) {
        const int r0 = m0 + wm + mt * 16 + g;
        const int r1 = r0 + 8;
        const int bi0 = r0 >> 9;
        const int bi1 = r1 >> 9;
        float p0 = 0.f, p1 = 0.f;
#pragma unroll
        for (int nt = 0; nt < 8; nt++) {
            const int n = n0 + wn + nt * 8 + tig * 2;
            const float v0 = v[n], v1 = v[n + 1];
            p0 = fmaf(v0, tanhf(acc[mt][nt][0] + Cb[(size_t)bi0 * Hd + n]), p0);
            p0 = fmaf(v1, tanhf(acc[mt][nt][1] + Cb[(size_t)bi0 * Hd + n + 1]), p0);
            p1 = fmaf(v0, tanhf(acc[mt][nt][2] + Cb[(size_t)bi1 * Hd + n]), p1);
            p1 = fmaf(v1, tanhf(acc[mt][nt][3] + Cb[(size_t)bi1 * Hd + n + 1]), p1);
        }
        p0 += __shfl_xor_sync(0xffffffffu, p0, 1);
        p0 += __shfl_xor_sync(0xffffffffu, p0, 2);
        p1 += __shfl_xor_sync(0xffffffffu, p1, 1);
        p1 += __shfl_xor_sync(0xffffffffu, p1, 2);
        if (tig == 0) {
            atomicAdd(&outp[r0], p0);
            atomicAdd(&outp[r1], p1);
        }
    }
}

// =================================================================================
// Skinny GEMM v2: warp = 4 columns x 16 rows; static register indexing only
// =================================================================================
struct SkJob {
    const float* A;
    const float* W;
    const float* bias;
    float* out;
    int lda, ldw, K, act;
};
struct SkJobs { SkJob j[4]; };

#define SK_CHUNK 128

__global__ __launch_bounds__(256) void skinny_gemm(SkJobs jobs) {
    const SkJob jb = jobs.j[blockIdx.y];
    __shared__ __align__(16) float As[64][SK_CHUNK];   // 32 KB
    const int tid = threadIdx.x, warp = tid >> 5, lane = tid & 31;
    const int nb = blockIdx.x * 8 + (warp & 1) * 4;    // 4 columns per warp
    const int r0 = (warp >> 1) * 16;                   // 16 rows per warp

    const float* w0 = jb.W + (size_t)(nb + 0) * jb.ldw;
    const float* w1 = jb.W + (size_t)(nb + 1) * jb.ldw;
    const float* w2 = jb.W + (size_t)(nb + 2) * jb.ldw;
    const float* w3 = jb.W + (size_t)(nb + 3) * jb.ldw;

    float acc[4][16];
#pragma unroll
    for (int c = 0; c < 4; c++)
#pragma unroll
        for (int r = 0; r < 16; r++) acc[c][r] = 0.f;

    for (int kc = 0; kc < jb.K; kc += SK_CHUNK) {
        __syncthreads();
#pragma unroll
        for (int it = 0; it < 8; it++) {
            int idx = tid + it * 256;
            int r = idx >> 5, cc = idx & 31;
            *(float4*)&As[r][cc * 4] =
                *(const float4*)(jb.A + (size_t)r * jb.lda + kc + cc * 4);
        }
        __syncthreads();
        const int ko = kc + lane * 4;
        float4 wv0 = *(const float4*)(w0 + ko);
        float4 wv1 = *(const float4*)(w1 + ko);
        float4 wv2 = *(const float4*)(w2 + ko);
        float4 wv3 = *(const float4*)(w3 + ko);
#pragma unroll
        for (int r = 0; r < 16; r++) {
            float4 a = *(const float4*)&As[r0 + r][lane * 4];
            acc[0][r] = fmaf(wv0.x, a.x, fmaf(wv0.y, a.y, fmaf(wv0.z, a.z, fmaf(wv0.w, a.w, acc[0][r]))));
            acc[1][r] = fmaf(wv1.x, a.x, fmaf(wv1.y, a.y, fmaf(wv1.z, a.z, fmaf(wv1.w, a.w, acc[1][r]))));
            acc[2][r] = fmaf(wv2.x, a.x, fmaf(wv2.y, a.y, fmaf(wv2.z, a.z, fmaf(wv2.w, a.w, acc[2][r]))));
            acc[3][r] = fmaf(wv3.x, a.x, fmaf(wv3.y, a.y, fmaf(wv3.z, a.z, fmaf(wv3.w, a.w, acc[3][r]))));
        }
    }
#pragma unroll
    for (int off = 16; off; off >>= 1)
#pragma unroll
        for (int c = 0; c < 4; c++)
#pragma unroll
            for (int r = 0; r < 16; r++)
                acc[c][r] += __shfl_xor_sync(0xffffffffu, acc[c][r], off);

    float bv0 = jb.bias[nb + 0], bv1 = jb.bias[nb + 1];
    float bv2 = jb.bias[nb + 2], bv3 = jb.bias[nb + 3];
#pragma unroll
    for (int r = 0; r < 16; r++) {
        if (lane == r) {
            float o0 = acc[0][r] + bv0, o1 = acc[1][r] + bv1;
            float o2 = acc[2][r] + bv2, o3 = acc[3][r] + bv3;
            if (jb.act == 1) { o0 = tanhf(o0); o1 = tanhf(o1); o2 = tanhf(o2); o3 = tanhf(o3); }
            float* op = jb.out + (size_t)(r0 + r) * Hd + nb;
            op[0] = o0; op[1] = o1; op[2] = o2; op[3] = o3;
        }
    }
}

// =================================================================================
// mma.sync TF32 fused GEMM (score heads)
// =================================================================================
#define BM 128
#define BN 128
#define BKt 32
#define PITCH 36

__global__ __launch_bounds__(256) void tf32_gemm_fused(
    const float* __restrict__ A, int lda, int amode, int rowmod,
    const float* __restrict__ leaf,
    const float* __restrict__ W, int ldw, int woff,
    const float* __restrict__ Cb, const float* __restrict__ v,
    float* __restrict__ out, int R, int K, int rows_per_b)
{
    __shared__ __align__(16) uint32_t As[BM * PITCH];
    __shared__ __align__(16) uint32_t Bs[BN * PITCH];

    const int tid = threadIdx.x;
    const int n0 = blockIdx.x * BN;
    const int m0 = blockIdx.y * BM;
    const int warp = tid >> 5, lane = tid & 31;
    const int g = lane >> 2, tig = lane & 3;
    const int wm = (warp >> 1) * 32;
    const int wn = (warp & 1) * 64;

    float acc[2][8][4];
#pragma unroll
    for (int mt = 0; mt < 2; mt++)
#pragma unroll
        for (int nt = 0; nt < 8; nt++)
#pragma unroll
            for (int c = 0; c < 4; c++) acc[mt][nt][c] = 0.f;

    for (int k0 = 0; k0 < K; k0 += BKt) {
#pragma unroll
        for (int it = 0; it < 4; it++) {
            int idx = tid + it * 256;
            int r = idx >> 3, c4 = idx & 7;
            int gr = m0 + r, gc = k0 + c4 * 4;
            float4 av = make_float4(0.f, 0.f, 0.f, 0.f);
            if (gr < R) {
                if (amode == 0) {
                    av = *(const float4*)(A + (size_t)gr * lda + gc);
                } else {
                    int xr = (amode == 2) ? (gr % rowmod) : gr;
                    if (gc < Hd) {
                        av = *(const float4*)(A + (size_t)xr * Hd + gc);
                    } else {
                        int h = gc - Hd;
                        int b = gr / rows_per_b;
                        av = *(const float4*)(A + (size_t)xr * Hd + h);
                        float4 lf = *(const float4*)(leaf + (size_t)b * Hd + h);
                        av.x *= lf.x; av.y *= lf.y; av.z *= lf.z; av.w *= lf.w;
                    }
                }
            }
            float4 bv = *(const float4*)(W + (size_t)(n0 + r) * ldw + woff + gc);
            uint4 ua, ub;
            ua.x = f2tf32(av.x); ua.y = f2tf32(av.y);
            ua.z = f2tf32(av.z); ua.w = f2tf32(av.w);
            ub.x = f2tf32(bv.x); ub.y = f2tf32(bv.y);
            ub.z = f2tf32(bv.z); ub.w = f2tf32(bv.w);
            *(uint4*)&As[r * PITCH + c4 * 4] = ua;
            *(uint4*)&Bs[r * PITCH + c4 * 4] = ub;
        }
        __syncthreads();

#pragma unroll
        for (int kk = 0; kk < BKt; kk += 8) {
            uint32_t af[2][4];
#pragma unroll
            for (int mt = 0; mt < 2; mt++) {
                int base = (wm + mt * 16 + g) * PITCH + kk;
                af[mt][0] = As[base + tig];
                af[mt][1] = As[base + 8 * PITCH + tig];
                af[mt][2] = As[base + tig + 4];
                af[mt][3] = As[base + 8 * PITCH + tig + 4];
            }
            uint32_t bf[8][2];
#pragma unroll
            for (int nt = 0; nt < 8; nt++) {
                int base = (wn + nt * 8 + g) * PITCH + kk;
                bf[nt][0] = Bs[base + tig];
                bf[nt][1] = Bs[base + tig + 4];
            }
#pragma unroll
            for (int mt = 0; mt < 2; mt++)
#pragma unroll
                for (int nt = 0; nt < 8; nt++) {
                    asm volatile(
                        "mma.sync.aligned.m16n8k8.row.col.f32.tf32.tf32.f32 "
                        "{%0,%1,%2,%3}, {%4,%5,%6,%7}, {%8,%9}, {%0,%1,%2,%3};"
                        : "+f"(acc[mt][nt][0]), "+f"(acc[mt][nt][1]),
                          "+f"(acc[mt][nt][2]), "+f"(acc[mt][nt][3])
                        : "r"(af[mt][0]), "r"(af[mt][1]), "r"(af[mt][2]), "r"(af[mt][3]),
                          "r"(bf[nt][0]), "r"(bf[nt][1]));
                }
        }
        __syncthreads();
    }

#pragma unroll
    for (int mt = 0; mt < 2; mt++) {
        int r0 = m0 + wm + mt * 16 + g;
        int r1 = r0 + 8;
        int bi0 = (r0 < R) ? (r0 / rows_per_b) : 0;
        int bi1 = (r1 < R) ? (r1 / rows_per_b) : 0;
        float p0 = 0.f, p1 = 0.f;
#pragma unroll
        for (int nt = 0; nt < 8; nt++) {
            int n = n0 + wn + nt * 8 + tig * 2;
            float v0 = v[n], v1 = v[n + 1];
            p0 = fmaf(v0, tanhf(acc[mt][nt][0] + Cb[(size_t)bi0 * Hd + n]), p0);
            p0 = fmaf(v1, tanhf(acc[mt][nt][1] + Cb[(size_t)bi0 * Hd + n + 1]), p0);
            p1 = fmaf(v0, tanhf(acc[mt][nt][2] + Cb[(size_t)bi1 * Hd + n]), p1);
            p1 = fmaf(v1, tanhf(acc[mt][nt][3] + Cb[(size_t)bi1 * Hd + n + 1]), p1);
        }
        p0 += __shfl_xor_sync(0xffffffffu, p0, 1);
        p0 += __shfl_xor_sync(0xffffffffu, p0, 2);
        p1 += __shfl_xor_sync(0xffffffffu, p1, 1);
        p1 += __shfl_xor_sync(0xffffffffu, p1, 2);
        if (tig == 0) {
            if (r0 < R) atomicAdd(&out[r0], p0);
            if (r1 < R) atomicAdd(&out[r1], p1);
        }
    }
}

// ---------------- small kernels ----------------
__global__ void init_kernel(const float* __restrict__ bs,
                            const float* __restrict__ left_childs,
                            const float* __restrict__ cur_emb)
{
    int i = blockIdx.x * blockDim.x + threadIdx.x;
    if (i < Bd * Sd) { g_energy[i] = bs[0]; return; }
    i -= Bd * Sd;
    if (i < Bd * (NTOT + OPd)) { g_spre[i] = 0.f; return; }
    i -= Bd * (NTOT + OPd);
    if (i < Bd * 2 * Hd) {
        int r = i >> 11, c = i & (2 * Hd - 1);
        g_lc[i] = (c < Hd) ? left_childs[r * Hd + c] : cur_emb[r * Hd + c - Hd];
    }
}

__global__ void node_kernel(const unsigned char* __restrict__ lm, float* o_node) {
    __shared__ int smode;
    if (threadIdx.x == 0) {
        int mode = 0;
        bool nonalign = false;
        for (int t = 1; t < 64; t++)
            if ((t & 3) && lm[t]) { nonalign = true; break; }
        if (nonalign) {
            const unsigned int* w = (const unsigned int*)lm;
            bool isf = true;
            for (int t = 0; t < 16; t++) {
                unsigned int x = w[t];
                if (x != 0u && x != 0x3F800000u) { isf = false; break; }
            }
            mode = isf ? 2 : 1;
        }
        smode = mode;
    }
    __syncthreads();
    int i = blockIdx.x * blockDim.x + threadIdx.x;
    if (i >= Bd * Hd) return;
    int b = i >> 10;
    bool m;
    if (smode == 1)      m = lm[b] != 0;
    else if (smode == 2) m = ((const float*)lm)[b] != 0.f;
    else                 m = ((const int*)lm)[b] != 0;
    float lv = tanhf(g_pre[i]) * (1.f / (1.f + expf(-g_pre[Bd * Hd + i])));
    float rv = tanhf(g_pre[2 * Bd * Hd + i]) * (1.f / (1.f + expf(-g_pre[3 * Bd * Hd + i])));
    float nv = m ? rv : lv;
    g_node[i] = nv;
    o_node[i] = nv;
    g_cat[(size_t)b * 2 * Hd + (i & (Hd - 1))] = nv;
}

__global__ void softmax_kernel(const int* __restrict__ seq_mask) {
    int b = blockIdx.x, s = threadIdx.x;
    __shared__ float red[Sd];
    float val = g_energy[b * Sd + s];
    if (seq_mask[b * Sd + s] == 0) val = NEGV;
    red[s] = val; __syncthreads();
    for (int off = Sd / 2; off > 0; off >>= 1) {
        if (s < off) red[s] = fmaxf(red[s], red[s + off]);
        __syncthreads();
    }
    float mx = red[0]; __syncthreads();
    float ex = expf(val - mx);
    red[s] = ex; __syncthreads();
    for (int off = Sd / 2; off > 0; off >>= 1) {
        if (s < off) red[s] += red[s + off];
        __syncthreads();
    }
    g_energy[b * Sd + s] = ex / red[0];
}

__global__ void ctx_kernel(const float* __restrict__ enc, float* o_ctx) {
    int b = blockIdx.x;
    int h = blockIdx.y * 128 + threadIdx.x;
    __shared__ float aw[Sd];
    for (int i = threadIdx.x; i < Sd; i += 128) aw[i] = g_energy[b * Sd + i];
    __syncthreads();
    const float* ep = enc + (size_t)b * Sd * Hd + h;
    float s0 = 0.f;
#pragma unroll 4
    for (int t = 0; t < Sd; t++) s0 = fmaf(aw[t], ep[(size_t)t * Hd], s0);
    o_ctx[b * Hd + h] = s0;
    g_cat[(size_t)b * 2 * Hd + Hd + h] = s0;
}

__global__ void constnum_kernel(const float* __restrict__ cemb,
                                const float* __restrict__ pades, float* o_cn) {
    int i = blockIdx.x * blockDim.x + threadIdx.x;
    if (i >= Bd * NTOT * Hd) return;
    int h = i & (Hd - 1);
    int rn = i >> 10;
    int n = rn % NTOT, b = rn / NTOT;
    o_cn[i] = (n < NCd) ? cemb[n * Hd + h]
                        : pades[((size_t)b * NNd + (n - NCd)) * Hd + h];
}

__global__ void fin_kernel(const int* __restrict__ mask_nums, float* o_num, float* o_op) {
    int i = blockIdx.x * blockDim.x + threadIdx.x;
    if (i < Bd * NTOT) o_num[i] = mask_nums[i] ? g_spre[i] : NEGV;
    if (i < Bd * OPd)  o_op[i]  = g_spre[Bd * NTOT + i];
}

// ---------------- launch ----------------
extern "C" void kernel_launch(void* const* d_in, const int* in_sizes, int n_in,
                              void* d_out, int out_size)
{
    const float* cur_emb     = (const float*)d_in[0];
    const float* left_childs = (const float*)d_in[1];
    const unsigned char* left_mask = (const unsigned char*)d_in[2];
    const float* enc         = (const float*)d_in[3];
    const float* num_pades   = (const float*)d_in[4];
    const int*   seq_mask    = (const int*)d_in[5];
    const int*   mask_nums   = (const int*)d_in[6];
    const float* cemb        = (const float*)d_in[7];
    const float* opemb       = (const float*)d_in[8];
    const float* Wl   = (const float*)d_in[9];
    const float* bl   = (const float*)d_in[10];
    const float* Wlg  = (const float*)d_in[11];
    const float* blg  = (const float*)d_in[12];
    const float* Wr   = (const float*)d_in[13];
    const float* br   = (const float*)d_in[14];
    const float* Wrg  = (const float*)d_in[15];
    const float* brg  = (const float*)d_in[16];
    const float* Wleaf= (const float*)d_in[17];
    const float* bleaf= (const float*)d_in[18];
    const float* Wa   = (const float*)d_in[19];
    const float* ba   = (const float*)d_in[20];
    const float* Ws   = (const float*)d_in[21];
    const float* bs   = (const float*)d_in[22];
    const float* Wna  = (const float*)d_in[23];
    const float* bna  = (const float*)d_in[24];
    const float* Wns  = (const float*)d_in[25];
    const float* Woa  = (const float*)d_in[26];
    const float* boa  = (const float*)d_in[27];
    const float* Wos  = (const float*)d_in[28];

    float* out   = (float*)d_out;
    float* o_num = out;
    float* o_op  = out + 2240;
    float* o_node= out + 2560;
    float* o_ctx = out + 68096;
    float* o_cn  = out + 133632;
    float* o_ope = out + 2427392;

    void* p;
    cudaGetSymbolAddress(&p, g_pre);     float* pre_    = (float*)p;
    cudaGetSymbolAddress(&p, g_lc);      float* lc_     = (float*)p;
    cudaGetSymbolAddress(&p, g_node);    float* node_   = (float*)p;
    cudaGetSymbolAddress(&p, g_cnode);   float* cnode_  = (float*)p;
    cudaGetSymbolAddress(&p, g_energy);  float* energy_ = (float*)p;
    cudaGetSymbolAddress(&p, g_cat);     float* cat_    = (float*)p;
    cudaGetSymbolAddress(&p, g_leaf);    float* leaf_   = (float*)p;
    cudaGetSymbolAddress(&p, g_cnum);    float* cnum_   = (float*)p;
    cudaGetSymbolAddress(&p, g_cop);     float* cop_    = (float*)p;
    cudaGetSymbolAddress(&p, g_spre);    float* spre_   = (float*)p;
    cudaGetSymbolAddress(&p, g_ench);    __half* ench_  = (__half*)p;
    cudaGetSymbolAddress(&p, g_wah);     __half* wah_   = (__half*)p;

    const int BH = Bd * Hd;

    cudaFuncSetAttribute(mma_energy_f16, cudaFuncAttributeMaxDynamicSharedMemorySize, FSMEM);

    // 1. fp16 convert pre-pass
    {
        int tot4 = (32768 * 1024 + 1024 * 1024) / 4;
        cvt_kernel<<<(tot4 + 255) / 256, 256>>>(enc, Wa);
    }

    // 2. init (energy seed / spre zero / lc concat)
    {
        int total = Bd * Sd + Bd * (NTOT + OPd) + 2 * BH;
        init_kernel<<<(total + 255) / 256, 256>>>(bs, left_childs, cur_emb);
    }

    // 3. node preacts
    {
        SkJobs js;
        js.j[0] = { cur_emb, Wl,  bl,  pre_,           Hd,     Hd,     Hd,     0 };
        js.j[1] = { cur_emb, Wlg, blg, pre_ + BH,      Hd,     Hd,     Hd,     0 };
        js.j[2] = { lc_,     Wr,  br,  pre_ + 2 * BH,  2 * Hd, 2 * Hd, 2 * Hd, 0 };
        js.j[3] = { lc_,     Wrg, brg, pre_ + 3 * BH,  2 * Hd, 2 * Hd, 2 * Hd, 0 };
        skinny_gemm<<<dim3(128, 4), 256>>>(js);
    }
    node_kernel<<<BH / 256, 256>>>(left_mask, o_node);

    // 4. cnode = ba + Wa[:, :H] @ node
    {
        SkJobs js;
        js.j[0] = { node_, Wa, ba, cnode_, Hd, 2 * Hd, Hd, 0 };
        skinny_gemm<<<dim3(128, 1), 256>>>(js);
    }

    // 5. attention energies via fp16 mma (2 CTAs/SM)
    mma_energy_f16<<<dim3(8, 256), 128, FSMEM>>>(ench_, wah_, cnode_, Ws, energy_);
    softmax_kernel<<<Bd, Sd>>>(seq_mask);
    dim3 gctx(Bd, 8);
    ctx_kernel<<<gctx, 128>>>(enc, o_ctx);

    // 6. const_num output (independent)
    constnum_kernel<<<(Bd * NTOT * Hd + 255) / 256, 256>>>(cemb, num_pades, o_cn);

    // 7. leaf
    {
        SkJobs js;
        js.j[0] = { cat_, Wleaf, bleaf, leaf_, 2 * Hd, 2 * Hd, 2 * Hd, 1 };
        skinny_gemm<<<dim3(128, 1), 256>>>(js);
    }

    // 8. per-batch score biases
    {
        SkJobs js;
        js.j[0] = { leaf_, Wna, bna, cnum_, Hd, 3 * Hd, Hd, 0 };
        js.j[1] = { leaf_, Woa, boa, cop_,  Hd, 3 * Hd, Hd, 0 };
        skinny_gemm<<<dim3(128, 2), 256>>>(js);
    }

    // 9. score heads (mma.sync TF32 fused)
    {
        dim3 gnum(8, (Bd * NTOT + BM - 1) / BM);
        tf32_gemm_fused<<<gnum, 256>>>(o_cn, 0, 1, 0, leaf_,
                                       Wna, 3 * Hd, Hd, cnum_, Wns,
                                       spre_, Bd * NTOT, 2 * Hd, NTOT);
        dim3 gop(8, (Bd * OPd + BM - 1) / BM);
        tf32_gemm_fused<<<gop, 256>>>(opemb, 0, 2, OPd, leaf_,
                                      Woa, 3 * Hd, Hd, cop_, Wos,
                                      spre_ + Bd * NTOT, Bd * OPd, 2 * Hd, OPd);
    }

    fin_kernel<<<(Bd * NTOT + 255) / 256, 256>>>(mask_nums, o_num, o_op);
    cudaMemcpyAsync(o_ope, opemb, OPd * Hd * sizeof(float), cudaMemcpyDeviceToDevice, 0);
}